// round 14
// baseline (speedup 1.0000x reference)
#include <cuda_runtime.h>
#include <math.h>
#include <stdint.h>

#define NB 2
#define NN 384
#define DD 128
#define NSQ (NN*NN)
#define ROWS_E (NB*NSQ)
#define ROWS_N (NB*NN)
#define T128 (ROWS_E/128)    // 2304
#define SCALE 0.08838834764831845f

__device__ __align__(256) float g_qkvn[ROWS_N*384];
__device__ __align__(256) float g_qkve[(size_t)ROWS_E*512];
__device__ __align__(256) float g_attn[ROWS_N*DD];
__device__ __align__(256) float g_mJ[ROWS_N*DD];
__device__ __align__(256) float g_mI[ROWS_N*DD];
__device__ __align__(256) float g_P[ROWS_N*DD];
__device__ __align__(256) float g_Q[ROWS_N*DD];
__device__ __align__(256) float g_buf[(size_t)ROWS_E*DD];
__device__ __align__(256) float g_h[(size_t)ROWS_E*256];

__device__ __forceinline__ float geluf(float x){return 0.5f*x*(1.f+erff(x*0.70710678118654752f));}
__device__ __forceinline__ float wsum(float v){
    #pragma unroll
    for(int o=16;o;o>>=1)v+=__shfl_xor_sync(0xffffffffu,v,o);return v;}
__device__ __forceinline__ float wmax(float v){
    #pragma unroll
    for(int o=16;o;o>>=1)v=fmaxf(v,__shfl_xor_sync(0xffffffffu,v,o));return v;}

__device__ __forceinline__ uint32_t smem_u32(const void* p){
    uint32_t a;asm("{ .reg .u64 t; cvta.to.shared.u64 t, %1; cvt.u32.u64 %0, t; }":"=r"(a):"l"(p));return a;}
__device__ __forceinline__ void split2(float a,float b,uint32_t&h,uint32_t&l){
    asm("cvt.rn.bf16x2.f32 %0,%1,%2;":"=r"(h):"f"(b),"f"(a));
    float ha=__uint_as_float(h<<16),hb=__uint_as_float(h&0xffff0000u);
    float la=a-ha,lb=b-hb;
    asm("cvt.rn.bf16x2.f32 %0,%1,%2;":"=r"(l):"f"(lb),"f"(la));}
__device__ __forceinline__ void ldsm4(uint32_t&r0,uint32_t&r1,uint32_t&r2,uint32_t&r3,uint32_t a){
    asm volatile("ldmatrix.sync.aligned.m8n8.x4.shared.b16 {%0,%1,%2,%3},[%4];"
        :"=r"(r0),"=r"(r1),"=r"(r2),"=r"(r3):"r"(a));}
__device__ __forceinline__ void mma16816(float* d,const uint32_t* a,uint32_t b0,uint32_t b1){
    asm volatile("mma.sync.aligned.m16n8k16.row.col.f32.bf16.bf16.f32 "
        "{%0,%1,%2,%3},{%4,%5,%6,%7},{%8,%9},{%0,%1,%2,%3};"
        :"+f"(d[0]),"+f"(d[1]),"+f"(d[2]),"+f"(d[3])
        :"r"(a[0]),"r"(a[1]),"r"(a[2]),"r"(a[3]),"r"(b0),"r"(b1));}

// ---- split-format conv: pure copy. src layout: [row][0..st/2) hi u32, [st/2..st) lo u32 ----
__device__ __forceinline__ void convCopy(const uint32_t* __restrict__ src,int st,int hi_off,
                                         size_t t,char* hi,char* lo,int tid){
    size_t r0=t*128;
    int m=tid>>1,hf=tid&1,x7=m&7;
    int lo_off=hi_off+(st>>1);
    const uint4* sh=(const uint4*)(src+(r0+m)*(size_t)st+hi_off)+hf*8;
    const uint4* sl=(const uint4*)(src+(r0+m)*(size_t)st+lo_off)+hf*8;
    char* rh=hi+m*256;char* rl=lo+m*256;
    #pragma unroll
    for(int i=0;i<8;i++){
        int g=hf*8+i;
        uint32_t off=(uint32_t)((g^x7)<<4);
        *(uint4*)(rh+off)=__ldg(sh+i);
        *(uint4*)(rl+off)=__ldg(sl+i);
    }
}

// weights: Wt[n][k]=W[k][w_cf+n] -> hi/lo swizzled, 128-k chunk, 256 threads
__device__ __forceinline__ void loadW(const float* __restrict__ W,int w_ld,int w_cf,
                                      char* Wh,char* Wl,int tid){
    int n=tid&127,kq=(tid>>7)*64;
    char* rh=Wh+n*256;char* rl=Wl+n*256;
    int nx7=n&7;
    #pragma unroll 4
    for(int kk=0;kk<64;kk+=2){
        int k=kq+kk;
        float w0=__ldg(W+(size_t)k*w_ld+w_cf+n);
        float w1=__ldg(W+(size_t)(k+1)*w_ld+w_cf+n);
        uint32_t h2,l2;split2(w0,w1,h2,l2);
        int kp=k>>1;
        uint32_t s=(uint32_t)((((kp>>2)^nx7)<<4)+((kp&3)<<2));
        *(uint32_t*)(rh+s)=h2;*(uint32_t*)(rl+s)=l2;
    }
}

// 64x32 warp-tile MMA over one 128-k chunk (accumulating)
__device__ __forceinline__ void mmaN32(float (&acc)[4][4][4],
    uint32_t AhU,uint32_t AlU,uint32_t WhU,uint32_t WlU,
    const uint32_t* rowA,uint32_t rowB0,uint32_t rowB1,int kh,int x7){
    #pragma unroll
    for(int ks=0;ks<8;ks++){
        uint32_t coff=(uint32_t)(((ks*2+kh)^x7)<<4);
        uint32_t ah[4][4],al[4][4];
        #pragma unroll
        for(int mf=0;mf<4;mf++){
            ldsm4(ah[mf][0],ah[mf][1],ah[mf][2],ah[mf][3],AhU+rowA[mf]+coff);
            ldsm4(al[mf][0],al[mf][1],al[mf][2],al[mf][3],AlU+rowA[mf]+coff);
        }
        uint32_t bh0,bh1,bh2,bh3,bl0,bl1,bl2,bl3;
        ldsm4(bh0,bh1,bh2,bh3,WhU+rowB0+coff);
        ldsm4(bl0,bl1,bl2,bl3,WlU+rowB0+coff);
        #pragma unroll
        for(int mf=0;mf<4;mf++){
            mma16816(acc[mf][0],ah[mf],bh0,bh2);mma16816(acc[mf][0],al[mf],bh0,bh2);mma16816(acc[mf][0],ah[mf],bl0,bl2);
            mma16816(acc[mf][1],ah[mf],bh1,bh3);mma16816(acc[mf][1],al[mf],bh1,bh3);mma16816(acc[mf][1],ah[mf],bl1,bl3);
        }
        ldsm4(bh0,bh1,bh2,bh3,WhU+rowB1+coff);
        ldsm4(bl0,bl1,bl2,bl3,WlU+rowB1+coff);
        #pragma unroll
        for(int mf=0;mf<4;mf++){
            mma16816(acc[mf][2],ah[mf],bh0,bh2);mma16816(acc[mf][2],al[mf],bh0,bh2);mma16816(acc[mf][2],ah[mf],bl0,bl2);
            mma16816(acc[mf][3],ah[mf],bh1,bh3);mma16816(acc[mf][3],al[mf],bh1,bh3);mma16816(acc[mf][3],ah[mf],bl1,bl3);
        }
    }
}

// ---- edge splitter: fp32 edge -> split planes (stride 128 u32/row) ----
__global__ __launch_bounds__(256) void k_split_edge(const float* __restrict__ edge,uint32_t* __restrict__ dst){
    int g=blockIdx.x*256+threadIdx.x;
    int row=g>>1,hf=g&1;
    const float4* src=(const float4*)edge+(size_t)row*32+hf*16;
    uint32_t* dh=dst+(size_t)row*128+hf*32;
    uint32_t* dl=dh+64;
    #pragma unroll
    for(int i=0;i<8;i++){
        float4 a=__ldg(src+2*i),b=__ldg(src+2*i+1);
        uint4 H,L;
        split2(a.x,a.y,H.x,L.x);split2(a.z,a.w,H.y,L.y);
        split2(b.x,b.y,H.z,L.z);split2(b.z,b.w,H.w,L.w);
        *(uint4*)(dh+i*4)=H;*(uint4*)(dl+i*4)=L;
    }
}

// ===================== unfused GEMM (N=128, 256 thr, split-A source) =====================
// MODE: 0=RAW fp32(direct), 4=LN(c+bias+add1+out_inplace) staged, 5=LN(c+bias+add1) staged + split copy to sdst
template<int MODE>
__global__ __launch_bounds__(256,1) void k_mm(
    const uint32_t* __restrict__ A,int a_st,int a_hi,
    const float* __restrict__ W,int w_ld,int w_cf,
    float* __restrict__ out,int o_st,int o_cf,
    const float* __restrict__ add1,const float* __restrict__ bias,
    const float* __restrict__ lng,const float* __restrict__ lnb,
    uint32_t* __restrict__ sdst)
{
    extern __shared__ char dyn[];
    char* base=(char*)((((uintptr_t)dyn)+1023)&~(uintptr_t)1023);
    char* Ah=base;char* Al=base+32768;
    char* Wh=base+65536;char* Wl=base+98304;
    float* stage=(float*)(base+131072);
    int tid=threadIdx.x,wp=tid>>5,lane=tid&31;
    int wr=wp>>2,wc=wp&3;
    int l15=lane&15,kh=lane>>4,x7=l15&7;

    loadW(W,w_ld,w_cf,Wh,Wl,tid);
    size_t t=blockIdx.x;
    if(t<T128)convCopy(A,a_st,a_hi,t,Ah,Al,tid);
    __syncthreads();
    uint32_t AhU=smem_u32(Ah),AlU=smem_u32(Al),WhU=smem_u32(Wh),WlU=smem_u32(Wl);
    uint32_t rowA[4];
    #pragma unroll
    for(int mf=0;mf<4;mf++)rowA[mf]=(uint32_t)(wr*64+mf*16+l15)*256;
    uint32_t rowB0=(uint32_t)(wc*32+l15)*256,rowB1=(uint32_t)(wc*32+16+l15)*256;

    for(;t<T128;t+=gridDim.x){
        float acc[4][4][4];
        #pragma unroll
        for(int mf=0;mf<4;mf++)
            #pragma unroll
            for(int ni=0;ni<4;ni++){acc[mf][ni][0]=0.f;acc[mf][ni][1]=0.f;acc[mf][ni][2]=0.f;acc[mf][ni][3]=0.f;}
        mmaN32(acc,AhU,AlU,WhU,WlU,rowA,rowB0,rowB1,kh,x7);
        size_t r0=t*128;
        if constexpr(MODE!=0){
            #pragma unroll
            for(int mf=0;mf<4;mf++){
                int row=wr*64+mf*16+(lane>>2);
                #pragma unroll
                for(int ni=0;ni<4;ni++){
                    int col=wc*32+ni*8+(lane&3)*2;
                    *(float2*)&stage[row*132+col]=make_float2(acc[mf][ni][0],acc[mf][ni][1]);
                    *(float2*)&stage[(row+8)*132+col]=make_float2(acc[mf][ni][2],acc[mf][ni][3]);
                }
            }
        }
        __syncthreads();
        size_t tn=t+gridDim.x;
        if(tn<T128)convCopy(A,a_st,a_hi,tn,Ah,Al,tid);
        if constexpr(MODE==0){
            #pragma unroll
            for(int mf=0;mf<4;mf++){
                #pragma unroll
                for(int ni=0;ni<4;ni++){
                    int col=o_cf+wc*32+ni*8+(lane&3)*2;
                    int rl=wr*64+mf*16+(lane>>2);
                    *(float2*)(out+((size_t)r0+rl)*o_st+col)=*(float2*)&acc[mf][ni][0];
                    *(float2*)(out+((size_t)r0+rl+8)*o_st+col)=*(float2*)&acc[mf][ni][2];
                }
            }
        }else{
            int m=tid>>1,hf=tid&1;
            size_t row=r0+m;
            const float* srow=stage+m*132+hf*64;
            float* orow=out+row*(size_t)o_st+o_cf+hf*64;
            const float* a1=add1+row*128+hf*64;
            const float* bi=bias+hf*64;
            float v[64];
            float s=0.f;
            #pragma unroll
            for(int n=0;n<64;n+=4){
                float4 c=*(const float4*)(srow+n);
                float4 a4=*(const float4*)(a1+n),b4=*(const float4*)(bi+n);
                v[n]=c.x+b4.x+a4.x;v[n+1]=c.y+b4.y+a4.y;
                v[n+2]=c.z+b4.z+a4.z;v[n+3]=c.w+b4.w+a4.w;
                if constexpr(MODE==4){
                    float4 t4=*(const float4*)(orow+n);
                    v[n]+=t4.x;v[n+1]+=t4.y;v[n+2]+=t4.z;v[n+3]+=t4.w;
                }
                s+=v[n]+v[n+1]+v[n+2]+v[n+3];
            }
            s+=__shfl_xor_sync(0xffffffffu,s,1);
            float mean=s*(1.f/128.f),s2=0.f;
            #pragma unroll
            for(int n=0;n<64;n++){v[n]-=mean;s2+=v[n]*v[n];}
            s2+=__shfl_xor_sync(0xffffffffu,s2,1);
            float rs=rsqrtf(s2*(1.f/128.f)+1e-5f);
            const float* gg=lng+hf*64;const float* bb2=lnb+hf*64;
            #pragma unroll
            for(int n=0;n<64;n+=4){
                float4 g4=*(const float4*)(gg+n),b4=*(const float4*)(bb2+n);
                float4 o;
                o.x=v[n]*rs*g4.x+b4.x;o.y=v[n+1]*rs*g4.y+b4.y;
                o.z=v[n+2]*rs*g4.z+b4.z;o.w=v[n+3]*rs*g4.w+b4.w;
                *(float4*)(orow+n)=o;
                if constexpr(MODE==5){
                    uint32_t h0,l0,h1,l1;
                    split2(o.x,o.y,h0,l0);split2(o.z,o.w,h1,l1);
                    int kp=hf*32+(n>>1);
                    uint32_t* dh=sdst+row*128+kp;
                    *(uint2*)dh=make_uint2(h0,h1);
                    *(uint2*)(dh+64)=make_uint2(l0,l1);
                }
            }
        }
        __syncthreads();
    }
}

// ===================== fused GEMM (N=256, 256 thr, warp 64x64, split-A) =====================
// MODE: 0=RAW fp32 out, 3=GELU + split out (stride 256 u32, hi kp / lo kp+128)
template<int MODE>
__global__ __launch_bounds__(256,1) void k_mm2(
    const uint32_t* __restrict__ A,int a_st,
    const float* __restrict__ W,int w_ld,int w_cf,
    float* __restrict__ out,int o_st,int o_cf)
{
    extern __shared__ char dyn[];
    char* base=(char*)((((uintptr_t)dyn)+1023)&~(uintptr_t)1023);
    char* Ah=base;char* Al=base+32768;
    int tid=threadIdx.x,wp=tid>>5,lane=tid&31;
    int wr=wp>>2,wc=wp&3;
    int l15=lane&15,kh=lane>>4,x7=l15&7;

    #pragma unroll
    for(int nb=0;nb<2;nb++)
        loadW(W,w_ld,w_cf+nb*128,base+65536+nb*65536,base+65536+nb*65536+32768,tid);
    size_t t=blockIdx.x;
    if(t<T128)convCopy(A,a_st,0,t,Ah,Al,tid);
    __syncthreads();
    uint32_t AhU=smem_u32(Ah),AlU=smem_u32(Al);
    uint32_t WhU=smem_u32(base+65536+(wc>>1)*65536),WlU=WhU+32768;
    uint32_t rowA[4];
    #pragma unroll
    for(int mf=0;mf<4;mf++)rowA[mf]=(uint32_t)(wr*64+mf*16+l15)*256;
    uint32_t rowB[4];
    #pragma unroll
    for(int nt=0;nt<4;nt++)rowB[nt]=(uint32_t)((wc&1)*64+nt*16+l15)*256;

    for(;t<T128;t+=gridDim.x){
        float acc[4][8][4];
        #pragma unroll
        for(int mf=0;mf<4;mf++)
            #pragma unroll
            for(int ni=0;ni<8;ni++){acc[mf][ni][0]=0.f;acc[mf][ni][1]=0.f;acc[mf][ni][2]=0.f;acc[mf][ni][3]=0.f;}
        #pragma unroll
        for(int ks=0;ks<8;ks++){
            uint32_t coff=(uint32_t)(((ks*2+kh)^x7)<<4);
            uint32_t ah[4][4],al[4][4];
            #pragma unroll
            for(int mf=0;mf<4;mf++){
                ldsm4(ah[mf][0],ah[mf][1],ah[mf][2],ah[mf][3],AhU+rowA[mf]+coff);
                ldsm4(al[mf][0],al[mf][1],al[mf][2],al[mf][3],AlU+rowA[mf]+coff);
            }
            #pragma unroll
            for(int nt=0;nt<4;nt++){
                uint32_t bh0,bh1,bh2,bh3,bl0,bl1,bl2,bl3;
                ldsm4(bh0,bh1,bh2,bh3,WhU+rowB[nt]+coff);
                ldsm4(bl0,bl1,bl2,bl3,WlU+rowB[nt]+coff);
                #pragma unroll
                for(int mf=0;mf<4;mf++){
                    mma16816(acc[mf][nt*2+0],ah[mf],bh0,bh2);mma16816(acc[mf][nt*2+0],al[mf],bh0,bh2);mma16816(acc[mf][nt*2+0],ah[mf],bl0,bl2);
                    mma16816(acc[mf][nt*2+1],ah[mf],bh1,bh3);mma16816(acc[mf][nt*2+1],al[mf],bh1,bh3);mma16816(acc[mf][nt*2+1],ah[mf],bl1,bl3);
                }
            }
        }
        __syncthreads();
        size_t tn=t+gridDim.x;
        if(tn<T128)convCopy(A,a_st,0,tn,Ah,Al,tid);
        size_t r0=t*128;
        if constexpr(MODE==0){
            #pragma unroll
            for(int mf=0;mf<4;mf++){
                #pragma unroll
                for(int ni=0;ni<8;ni++){
                    int col=o_cf+wc*64+ni*8+(lane&3)*2;
                    int rl=wr*64+mf*16+(lane>>2);
                    *(float2*)(out+((size_t)r0+rl)*o_st+col)=*(float2*)&acc[mf][ni][0];
                    *(float2*)(out+((size_t)r0+rl+8)*o_st+col)=*(float2*)&acc[mf][ni][2];
                }
            }
        }else{
            uint32_t* outu=(uint32_t*)out;
            #pragma unroll
            for(int mf=0;mf<4;mf++){
                #pragma unroll
                for(int ni=0;ni<8;ni++){
                    int kp=wc*32+ni*4+(lane&3);
                    int rl=wr*64+mf*16+(lane>>2);
                    float a0=geluf(acc[mf][ni][0]),a1=geluf(acc[mf][ni][1]);
                    float a2=geluf(acc[mf][ni][2]),a3=geluf(acc[mf][ni][3]);
                    uint32_t h0,l0,h1,l1;
                    split2(a0,a1,h0,l0);split2(a2,a3,h1,l1);
                    outu[((size_t)r0+rl)*256+kp]=h0;outu[((size_t)r0+rl)*256+128+kp]=l0;
                    outu[((size_t)r0+rl+8)*256+kp]=h1;outu[((size_t)r0+rl+8)*256+128+kp]=l1;
                }
            }
        }
        __syncthreads();
    }
}

// ===================== e1 merged K=256 kernel (split-edge direct + transposed) =====================
__global__ __launch_bounds__(256,1) void k_e1K2(
    const uint32_t* __restrict__ se,const float* __restrict__ We,const float* __restrict__ be,
    uint32_t* __restrict__ outu)
{
    extern __shared__ char dyn[];
    char* base=(char*)((((uintptr_t)dyn)+1023)&~(uintptr_t)1023);
    char* Ah=base;char* Al=base+32768;
    int tid=threadIdx.x,wp=tid>>5,lane=tid&31;
    int wr=wp>>2,wc=wp&3;
    int l15=lane&15,kh=lane>>4,x7=l15&7;

    loadW(We,128,0,base+65536,base+98304,tid);
    loadW(We+(size_t)128*128,128,0,base+131072,base+163840,tid);
    __syncthreads();
    uint32_t AhU=smem_u32(Ah),AlU=smem_u32(Al);
    uint32_t W0h=smem_u32(base+65536),W0l=smem_u32(base+98304);
    uint32_t W1h=smem_u32(base+131072),W1l=smem_u32(base+163840);
    uint32_t rowA[4];
    #pragma unroll
    for(int mf=0;mf<4;mf++)rowA[mf]=(uint32_t)(wr*64+mf*16+l15)*256;
    uint32_t rowB0=(uint32_t)(wc*32+l15)*256,rowB1=(uint32_t)(wc*32+16+l15)*256;

    for(size_t t=blockIdx.x;t<T128;t+=gridDim.x){
        size_t r0=t*128;
        int bb=(int)(r0/NSQ),rem=(int)(r0%NSQ),iI=rem/NN,j0=rem%NN;
        convCopy(se,128,0,t,Ah,Al,tid);
        __syncthreads();
        float acc[4][4][4];
        #pragma unroll
        for(int mf=0;mf<4;mf++)
            #pragma unroll
            for(int ni=0;ni<4;ni++){acc[mf][ni][0]=0.f;acc[mf][ni][1]=0.f;acc[mf][ni][2]=0.f;acc[mf][ni][3]=0.f;}
        mmaN32(acc,AhU,AlU,W0h,W0l,rowA,rowB0,rowB1,kh,x7);
        __syncthreads();
        {   // transposed chunk copy
            int m=tid>>1,hf=tid&1,mx7=m&7;
            size_t srow=((size_t)(bb*NN+(j0+m))*NN+iI);
            const uint4* sh=(const uint4*)(se+srow*128)+hf*8;
            const uint4* sl=(const uint4*)(se+srow*128+64)+hf*8;
            char* rh=Ah+m*256;char* rl=Al+m*256;
            #pragma unroll
            for(int i=0;i<8;i++){
                int g=hf*8+i;
                uint32_t off=(uint32_t)((g^mx7)<<4);
                *(uint4*)(rh+off)=__ldg(sh+i);
                *(uint4*)(rl+off)=__ldg(sl+i);
            }
        }
        __syncthreads();
        mmaN32(acc,AhU,AlU,W1h,W1l,rowA,rowB0,rowB1,kh,x7);
        __syncthreads();
        {
            const float* Pr=g_P+(size_t)(bb*NN+iI)*128;
            #pragma unroll
            for(int mf=0;mf<4;mf++){
                #pragma unroll
                for(int ni=0;ni<4;ni++){
                    int col=wc*32+ni*8+(lane&3)*2;
                    int kp=col>>1;
                    float2 p2=*(const float2*)(Pr+col);
                    float2 b2=*(const float2*)(be+col);
                    #pragma unroll
                    for(int h=0;h<2;h++){
                        int row=wr*64+mf*16+(lane>>2)+h*8;
                        float2 c=*(float2*)&acc[mf][ni][h*2];
                        float2 q2=*(const float2*)(g_Q+(size_t)(bb*NN+j0+row)*128+col);
                        float ox=geluf(c.x+b2.x+p2.x+q2.x);
                        float oy=geluf(c.y+b2.y+p2.y+q2.y);
                        uint32_t hh,ll;split2(ox,oy,hh,ll);
                        outu[((size_t)r0+row)*128+kp]=hh;
                        outu[((size_t)r0+row)*128+64+kp]=ll;
                    }
                }
            }
        }
    }
}

// ===================== small fp32 kernels =====================
__global__ __launch_bounds__(384) void k_qkvn(const float* __restrict__ node,const float* __restrict__ W){
    int row=blockIdx.x,c=threadIdx.x;
    __shared__ float s[DD];
    if(c<DD)s[c]=node[row*DD+c];
    __syncthreads();
    float a=0.f;
    #pragma unroll 8
    for(int k=0;k<DD;k++)a+=s[k]*W[k*384+c];
    g_qkvn[row*384+c]=a;
}

__global__ __launch_bounds__(128) void k_attn(){
    int w=threadIdx.x>>5,lane=threadIdx.x&31;
    int gw=blockIdx.x*4+w;
    int b=gw/(8*NN),rr=gw%(8*NN),h=rr/NN,i=rr%NN;
    const float* qb=g_qkvn+(b*NN+i)*384+h*48;
    float qv[16];
    #pragma unroll
    for(int c=0;c<16;c++)qv[c]=qb[c];
    const float* eb=g_qkve+((size_t)(b*NN+i)*NN)*512+h*64;
    float dl[12];
    #pragma unroll
    for(int t=0;t<12;t++){
        int j=lane+32*t;
        const float4* e4=(const float4*)(eb+(size_t)j*512);
        const float4* k4=(const float4*)(g_qkvn+(b*NN+j)*384+h*48+16);
        float d=0.f;
        #pragma unroll
        for(int q=0;q<4;q++){
            float4 eq=e4[q],ek=e4[4+q],kk=k4[q];
            d+=(qv[4*q]+eq.x)*(kk.x+ek.x)+(qv[4*q+1]+eq.y)*(kk.y+ek.y)
              +(qv[4*q+2]+eq.z)*(kk.z+ek.z)+(qv[4*q+3]+eq.w)*(kk.w+ek.w);
        }
        dl[t]=d*SCALE;
    }
    float m=dl[0];
    #pragma unroll
    for(int t=1;t<12;t++)m=fmaxf(m,dl[t]);
    m=wmax(m);
    float s=0.f,out[16];
    #pragma unroll
    for(int c=0;c<16;c++)out[c]=0.f;
    #pragma unroll
    for(int t=0;t<12;t++){
        int j=lane+32*t;
        float p=__expf(dl[t]-m);s+=p;
        const float4* e4=(const float4*)(eb+(size_t)j*512);
        const float4* v4=(const float4*)(g_qkvn+(b*NN+j)*384+h*48+32);
        #pragma unroll
        for(int q=0;q<4;q++){
            float4 ev=e4[8+q],em=e4[12+q],vn=v4[q];
            out[4*q]+=p*(vn.x*em.x+ev.x);out[4*q+1]+=p*(vn.y*em.y+ev.y);
            out[4*q+2]+=p*(vn.z*em.z+ev.z);out[4*q+3]+=p*(vn.w*em.w+ev.w);
        }
    }
    s=wsum(s);
    float inv=1.f/s;
    #pragma unroll
    for(int c=0;c<16;c++){
        float v=wsum(out[c]);
        if(lane==0)g_attn[(b*NN+i)*DD+h*16+c]=v*inv;
    }
}

__global__ __launch_bounds__(128) void k_node(const float* __restrict__ node,const float* __restrict__ w0,const float* __restrict__ b0,
    const float* __restrict__ g0,const float* __restrict__ be0,const float* __restrict__ g1,const float* __restrict__ be1,
    const float* __restrict__ w1,const float* __restrict__ w2,const float* __restrict__ b2,float* __restrict__ x){
    int row=blockIdx.x,c=threadIdx.x;
    __shared__ float sa[DD],sx[DD],sh[256],sr[8];
    sa[c]=g_attn[row*DD+c];
    __syncthreads();
    float y=b0[c];
    #pragma unroll 4
    for(int k=0;k<DD;k++)y+=sa[k]*w0[k*DD+c];
    float r=node[row*DD+c]+y;
    float t=wsum(r);if((c&31)==0)sr[c>>5]=t;__syncthreads();
    float mean=(sr[0]+sr[1]+sr[2]+sr[3])*(1.f/DD);
    float d=r-mean;
    t=wsum(d*d);if((c&31)==0)sr[4+(c>>5)]=t;__syncthreads();
    float x0=d*rsqrtf((sr[4]+sr[5]+sr[6]+sr[7])*(1.f/DD)+1e-5f)*g0[c]+be0[c];
    sx[c]=x0;__syncthreads();
    float h0=0.f,h1=0.f;
    #pragma unroll 4
    for(int k=0;k<DD;k++){float v=sx[k];h0+=v*w1[k*256+c];h1+=v*w1[k*256+c+128];}
    sh[c]=geluf(h0);sh[c+128]=geluf(h1);
    __syncthreads();
    float z=b2[c];
    #pragma unroll 4
    for(int k=0;k<256;k++)z+=sh[k]*w2[k*DD+c];
    float r2=x0+z;
    __syncthreads();
    t=wsum(r2);if((c&31)==0)sr[c>>5]=t;__syncthreads();
    float m2=(sr[0]+sr[1]+sr[2]+sr[3])*(1.f/DD);
    float d2=r2-m2;
    t=wsum(d2*d2);if((c&31)==0)sr[4+(c>>5)]=t;__syncthreads();
    x[row*DD+c]=d2*rsqrtf((sr[4]+sr[5]+sr[6]+sr[7])*(1.f/DD)+1e-5f)*g1[c]+be1[c];
}

__global__ __launch_bounds__(128) void k_means(const float* __restrict__ edge){
    int bi=blockIdx.x,c=threadIdx.x,b=bi/NN,r=bi%NN;
    float s=0.f;
    if(blockIdx.y==0){
        const float* p=edge+((size_t)(b*NN+r)*NN)*DD+c;
        for(int j=0;j<NN;j++)s+=p[(size_t)j*DD];
        g_mJ[bi*DD+c]=s*(1.f/NN);
    }else{
        const float* p=edge+((size_t)b*NSQ+r)*DD+c;
        for(int i=0;i<NN;i++)s+=p[(size_t)i*NN*DD];
        g_mI[bi*DD+c]=s*(1.f/NN);
    }
}

__global__ __launch_bounds__(128) void k_PQ(const float* __restrict__ x,const float* __restrict__ ws,const float* __restrict__ bs,
    const float* __restrict__ wt,const float* __restrict__ bt,const float* __restrict__ wer,const float* __restrict__ wec){
    int bi=blockIdx.x,c=threadIdx.x;
    __shared__ float sx[DD],sj[DD],si[DD];
    sx[c]=x[bi*DD+c];sj[c]=g_mJ[bi*DD+c];si[c]=g_mI[bi*DD+c];
    __syncthreads();
    float P=bs[c],Q=bt[c];
    #pragma unroll 4
    for(int k=0;k<DD;k++){
        P+=sx[k]*ws[k*DD+c]+sj[k]*wer[k*DD+c];
        Q+=sx[k]*wt[k*DD+c]+si[k]*wec[k*DD+c];
    }
    g_P[bi*DD+c]=P;g_Q[bi*DD+c]=Q;
}

extern "C" void kernel_launch(void* const* d_in,const int* in_sizes,int n_in,void* d_out,int out_size){
    const float* node=(const float*)d_in[0];
    const float* edge=(const float*)d_in[1];
    const float* wqkvn=(const float*)d_in[3];
    const float* wqkve=(const float*)d_in[4];
    const float* lin0w=(const float*)d_in[5];
    const float* lin0b=(const float*)d_in[6];
    const float* ln0g=(const float*)d_in[7];
    const float* ln0b=(const float*)d_in[8];
    const float* ln1g=(const float*)d_in[9];
    const float* ln1b=(const float*)d_in[10];
    const float* w1=(const float*)d_in[11];
    const float* w2=(const float*)d_in[12];
    const float* b2=(const float*)d_in[13];
    const float* e0we=(const float*)d_in[14];
    const float* e0be=(const float*)d_in[15];
    const float* e0ws=(const float*)d_in[16];
    const float* e0bs=(const float*)d_in[17];
    const float* e0wt=(const float*)d_in[18];
    const float* e0bt=(const float*)d_in[19];
    const float* e0wer=(const float*)d_in[20];
    const float* e0wec=(const float*)d_in[21];
    const float* e0w1=(const float*)d_in[22];
    const float* e0b1=(const float*)d_in[23];
    const float* e1w1=(const float*)d_in[24];
    const float* e1w2=(const float*)d_in[25];
    const float* e1b2=(const float*)d_in[26];
    const float* eln0g=(const float*)d_in[27];
    const float* eln0b=(const float*)d_in[28];
    const float* eln1g=(const float*)d_in[29];
    const float* eln1b=(const float*)d_in[30];
    float* xout=(float*)d_out;
    float* eout=(float*)d_out+(size_t)ROWS_N*DD;

    const int SM_SMALL=131072+1024;
    const int SM_STAGE=131072+132*128*4+1024;
    const int SM_BIG=196608+1024;
    cudaFuncSetAttribute(k_mm<0>,cudaFuncAttributeMaxDynamicSharedMemorySize,SM_SMALL);
    cudaFuncSetAttribute(k_mm<4>,cudaFuncAttributeMaxDynamicSharedMemorySize,SM_STAGE);
    cudaFuncSetAttribute(k_mm<5>,cudaFuncAttributeMaxDynamicSharedMemorySize,SM_STAGE);
    cudaFuncSetAttribute(k_mm2<0>,cudaFuncAttributeMaxDynamicSharedMemorySize,SM_BIG);
    cudaFuncSetAttribute(k_mm2<3>,cudaFuncAttributeMaxDynamicSharedMemorySize,SM_BIG);
    cudaFuncSetAttribute(k_e1K2,cudaFuncAttributeMaxDynamicSharedMemorySize,SM_BIG);

    float *gq,*gh,*gb;
    cudaGetSymbolAddress((void**)&gq,g_qkve);
    cudaGetSymbolAddress((void**)&gh,g_h);
    cudaGetSymbolAddress((void**)&gb,g_buf);
    uint32_t* se=(uint32_t*)gh;      // split-edge (g_h phase 1)
    uint32_t* sbuf=(uint32_t*)gb;    // split e1-out (g_buf phase 1)
    uint32_t* seo=(uint32_t*)gq;     // split eout (g_qkve phase 2)
    uint32_t* shh=(uint32_t*)gh;     // split h (g_h phase 2)

    k_qkvn<<<ROWS_N,384>>>(node,wqkvn);
    k_split_edge<<<ROWS_E*2/256,256>>>(edge,se);
    for(int q=0;q<2;q++)
        k_mm2<0><<<148,256,SM_BIG>>>(se,128, wqkve,512,q*256, gq,512,q*256);
    k_means<<<dim3(ROWS_N,2),128>>>(edge);
    k_attn<<<ROWS_N*8/4,128>>>();
    k_node<<<ROWS_N,128>>>(node,lin0w,lin0b,ln0g,ln0b,ln1g,ln1b,w1,w2,b2,xout);
    k_PQ<<<ROWS_N,128>>>(xout,e0ws,e0bs,e0wt,e0bt,e0wer,e0wec);
    k_e1K2<<<148,256,SM_BIG>>>(se,e0we,e0be,sbuf);
    k_mm<5><<<148,256,SM_STAGE>>>(sbuf,128,0, e0w1,128,0, eout,128,0, edge,e0b1,eln0g,eln0b, seo);
    k_mm2<3><<<148,256,SM_BIG>>>(seo,128, e1w1,256,0, gh,256,0);
    k_mm<0><<<148,256,SM_SMALL>>>(shh,256,0, e1w2,128,0, gb,128,0, nullptr,nullptr,nullptr,nullptr,nullptr);
    k_mm<4><<<148,256,SM_STAGE>>>(shh,256,64, e1w2+(size_t)128*128,128,0, eout,128,0, gb,e1b2,eln1g,eln1b, nullptr);
}

// round 15
// speedup vs baseline: 1.0905x; 1.0905x over previous
#include <cuda_runtime.h>
#include <math.h>
#include <stdint.h>

#define NB 2
#define NN 384
#define DD 128
#define NSQ (NN*NN)
#define ROWS_E (NB*NSQ)
#define ROWS_N (NB*NN)
#define T128 (ROWS_E/128)    // 2304
#define SCALE 0.08838834764831845f

__device__ __align__(256) float g_qkvn[ROWS_N*384];
__device__ __align__(256) float g_qkve[(size_t)ROWS_E*512];
__device__ __align__(256) float g_attn[ROWS_N*DD];
__device__ __align__(256) float g_mJ[ROWS_N*DD];
__device__ __align__(256) float g_mI[ROWS_N*DD];
__device__ __align__(256) float g_P[ROWS_N*DD];
__device__ __align__(256) float g_Q[ROWS_N*DD];
__device__ __align__(256) float g_buf[(size_t)ROWS_E*DD];
__device__ __align__(256) float g_h[(size_t)ROWS_E*256];

__device__ __forceinline__ float geluf(float x){return 0.5f*x*(1.f+erff(x*0.70710678118654752f));}
__device__ __forceinline__ float wsum(float v){
    #pragma unroll
    for(int o=16;o;o>>=1)v+=__shfl_xor_sync(0xffffffffu,v,o);return v;}
__device__ __forceinline__ float wmax(float v){
    #pragma unroll
    for(int o=16;o;o>>=1)v=fmaxf(v,__shfl_xor_sync(0xffffffffu,v,o));return v;}

__device__ __forceinline__ uint32_t smem_u32(const void* p){
    uint32_t a;asm("{ .reg .u64 t; cvta.to.shared.u64 t, %1; cvt.u32.u64 %0, t; }":"=r"(a):"l"(p));return a;}
__device__ __forceinline__ void split2(float a,float b,uint32_t&h,uint32_t&l){
    asm("cvt.rn.bf16x2.f32 %0,%1,%2;":"=r"(h):"f"(b),"f"(a));
    float ha=__uint_as_float(h<<16),hb=__uint_as_float(h&0xffff0000u);
    float la=a-ha,lb=b-hb;
    asm("cvt.rn.bf16x2.f32 %0,%1,%2;":"=r"(l):"f"(lb),"f"(la));}
__device__ __forceinline__ void ldsm4(uint32_t&r0,uint32_t&r1,uint32_t&r2,uint32_t&r3,uint32_t a){
    asm volatile("ldmatrix.sync.aligned.m8n8.x4.shared.b16 {%0,%1,%2,%3},[%4];"
        :"=r"(r0),"=r"(r1),"=r"(r2),"=r"(r3):"r"(a));}
__device__ __forceinline__ void mma16816(float* d,const uint32_t* a,uint32_t b0,uint32_t b1){
    asm volatile("mma.sync.aligned.m16n8k16.row.col.f32.bf16.bf16.f32 "
        "{%0,%1,%2,%3},{%4,%5,%6,%7},{%8,%9},{%0,%1,%2,%3};"
        :"+f"(d[0]),"+f"(d[1]),"+f"(d[2]),"+f"(d[3])
        :"r"(a[0]),"r"(a[1]),"r"(a[2]),"r"(a[3]),"r"(b0),"r"(b1));}

// split-format conv (pure copy), 512 threads: 4 per row, 4 uint4 hi + 4 lo each
// src row layout: [hi_off .. hi_off+st/2) hi u32, [hi_off+st/2 ..) lo u32
template<bool TRANS>
__device__ __forceinline__ void convCopy(const uint32_t* __restrict__ src,int st,int hi_off,
                                         size_t t,char* hi,char* lo,int tid){
    size_t r0=t*128;
    int m=tid>>2,q=tid&3,x7=m&7;
    size_t row;
    if(TRANS){
        int bb=(int)(r0/NSQ),rem=(int)(r0%NSQ),iI=rem/NN,j0=rem%NN;
        row=((size_t)(bb*NN+(j0+m))*NN+iI);
    }else row=r0+m;
    const uint4* sh=(const uint4*)(src+row*(size_t)st+hi_off)+q*4;
    const uint4* sl=(const uint4*)(src+row*(size_t)st+hi_off+(st>>1))+q*4;
    char* rh=hi+m*256;char* rl=lo+m*256;
    #pragma unroll
    for(int i=0;i<4;i++){
        int g=q*4+i;
        uint32_t off=(uint32_t)((g^x7)<<4);
        *(uint4*)(rh+off)=__ldg(sh+i);
        *(uint4*)(rl+off)=__ldg(sl+i);
    }
}

// weights: Wt[n][k]=W[k][w_cf+n] -> hi/lo swizzled, 128-k chunk, 512 threads (4 k-quarters)
__device__ __forceinline__ void loadW(const float* __restrict__ W,int w_ld,int w_cf,
                                      char* Wh,char* Wl,int tid){
    int n=tid&127,kq=(tid>>7)*32;
    char* rh=Wh+n*256;char* rl=Wl+n*256;
    int nx7=n&7;
    #pragma unroll
    for(int kk=0;kk<32;kk+=2){
        int k=kq+kk;
        float w0=__ldg(W+(size_t)k*w_ld+w_cf+n);
        float w1=__ldg(W+(size_t)(k+1)*w_ld+w_cf+n);
        uint32_t h2,l2;split2(w0,w1,h2,l2);
        int kp=k>>1;
        uint32_t s=(uint32_t)((((kp>>2)^nx7)<<4)+((kp&3)<<2));
        *(uint32_t*)(rh+s)=h2;*(uint32_t*)(rl+s)=l2;
    }
}

// ---- edge splitter: fp32 edge -> split planes (stride 128 u32/row) ----
__global__ __launch_bounds__(256) void k_split_edge(const float* __restrict__ edge,uint32_t* __restrict__ dst){
    int g=blockIdx.x*256+threadIdx.x;
    int row=g>>1,hf=g&1;
    const float4* src=(const float4*)edge+(size_t)row*32+hf*16;
    uint32_t* dh=dst+(size_t)row*128+hf*32;
    uint32_t* dl=dh+64;
    #pragma unroll
    for(int i=0;i<8;i++){
        float4 a=__ldg(src+2*i),b=__ldg(src+2*i+1);
        uint4 H,L;
        split2(a.x,a.y,H.x,L.x);split2(a.z,a.w,H.y,L.y);
        split2(b.x,b.y,H.z,L.z);split2(b.z,b.w,H.w,L.w);
        *(uint4*)(dh+i*4)=H;*(uint4*)(dl+i*4)=L;
    }
}

// ===================== unfused GEMM (N=128, 512 thr, warp 32x32, R10 tiles) =====================
// MODE: 0=RAW fp32 direct, 1=E1 gelu(c+bias+add1+P+Q) split-out, 4=LN(c+b+add1+out) staged, 5=LN(c+b+add1) staged + split copy
template<int MODE,bool TRANS>
__global__ __launch_bounds__(512,1) void k_mm(
    const uint32_t* __restrict__ A,int a_st,int a_hi,
    const float* __restrict__ W,int w_ld,int w_cf,
    float* __restrict__ out,int o_st,int o_cf,
    const float* __restrict__ add1,const float* __restrict__ bias,
    const float* __restrict__ lng,const float* __restrict__ lnb,
    uint32_t* __restrict__ sdst)
{
    extern __shared__ char dyn[];
    char* base=(char*)((((uintptr_t)dyn)+1023)&~(uintptr_t)1023);
    char* Ah=base;char* Al=base+32768;
    char* Wh=base+65536;char* Wl=base+98304;
    float* stage=(float*)(base+131072);
    int tid=threadIdx.x,wp=tid>>5,lane=tid&31;
    int wr=wp>>2,wc=wp&3;
    int l15=lane&15,kh=lane>>4,x7=l15&7;

    loadW(W,w_ld,w_cf,Wh,Wl,tid);
    size_t t=blockIdx.x;
    if(t<T128)convCopy<TRANS>(A,a_st,a_hi,t,Ah,Al,tid);
    __syncthreads();
    uint32_t AhU=smem_u32(Ah),AlU=smem_u32(Al),WhU=smem_u32(Wh),WlU=smem_u32(Wl);
    uint32_t rowA0=(uint32_t)(wr*32+l15)*256,rowA1=(uint32_t)(wr*32+16+l15)*256;
    uint32_t rowB0=(uint32_t)(wc*32+l15)*256,rowB1=(uint32_t)(wc*32+16+l15)*256;

    for(;t<T128;t+=gridDim.x){
        float acc[2][4][4];
        #pragma unroll
        for(int mi=0;mi<2;mi++)
            #pragma unroll
            for(int ni=0;ni<4;ni++){acc[mi][ni][0]=0.f;acc[mi][ni][1]=0.f;acc[mi][ni][2]=0.f;acc[mi][ni][3]=0.f;}
        #pragma unroll 2
        for(int ks=0;ks<8;ks++){
            uint32_t coff=(uint32_t)(((ks*2+kh)^x7)<<4);
            uint32_t ah[2][4],al[2][4];
            ldsm4(ah[0][0],ah[0][1],ah[0][2],ah[0][3],AhU+rowA0+coff);
            ldsm4(ah[1][0],ah[1][1],ah[1][2],ah[1][3],AhU+rowA1+coff);
            ldsm4(al[0][0],al[0][1],al[0][2],al[0][3],AlU+rowA0+coff);
            ldsm4(al[1][0],al[1][1],al[1][2],al[1][3],AlU+rowA1+coff);
            uint32_t bh0,bh1,bh2,bh3,bl0,bl1,bl2,bl3;
            ldsm4(bh0,bh1,bh2,bh3,WhU+rowB0+coff);
            ldsm4(bl0,bl1,bl2,bl3,WlU+rowB0+coff);
            #pragma unroll
            for(int mi=0;mi<2;mi++){
                mma16816(acc[mi][0],ah[mi],bh0,bh2);mma16816(acc[mi][0],al[mi],bh0,bh2);mma16816(acc[mi][0],ah[mi],bl0,bl2);
                mma16816(acc[mi][1],ah[mi],bh1,bh3);mma16816(acc[mi][1],al[mi],bh1,bh3);mma16816(acc[mi][1],ah[mi],bl1,bl3);
            }
            ldsm4(bh0,bh1,bh2,bh3,WhU+rowB1+coff);
            ldsm4(bl0,bl1,bl2,bl3,WlU+rowB1+coff);
            #pragma unroll
            for(int mi=0;mi<2;mi++){
                mma16816(acc[mi][2],ah[mi],bh0,bh2);mma16816(acc[mi][2],al[mi],bh0,bh2);mma16816(acc[mi][2],ah[mi],bl0,bl2);
                mma16816(acc[mi][3],ah[mi],bh1,bh3);mma16816(acc[mi][3],al[mi],bh1,bh3);mma16816(acc[mi][3],ah[mi],bl1,bl3);
            }
        }
        size_t r0=t*128;
        if constexpr(MODE==4||MODE==5){
            #pragma unroll
            for(int mi=0;mi<2;mi++){
                int row=wr*32+mi*16+(lane>>2);
                #pragma unroll
                for(int ni=0;ni<4;ni++){
                    int col=wc*32+ni*8+(lane&3)*2;
                    *(float2*)&stage[row*132+col]=make_float2(acc[mi][ni][0],acc[mi][ni][1]);
                    *(float2*)&stage[(row+8)*132+col]=make_float2(acc[mi][ni][2],acc[mi][ni][3]);
                }
            }
        }
        __syncthreads();
        size_t tn=t+gridDim.x;
        if(tn<T128)convCopy<TRANS>(A,a_st,a_hi,tn,Ah,Al,tid);
        if constexpr(MODE==0){
            #pragma unroll
            for(int ni=0;ni<4;ni++){
                int col=o_cf+wc*32+ni*8+(lane&3)*2;
                #pragma unroll
                for(int mi=0;mi<2;mi++){
                    int rl=wr*32+mi*16+(lane>>2);
                    *(float2*)(out+((size_t)r0+rl)*o_st+col)=*(float2*)&acc[mi][ni][0];
                    *(float2*)(out+((size_t)r0+rl+8)*o_st+col)=*(float2*)&acc[mi][ni][2];
                }
            }
        }else if constexpr(MODE==1){
            int bb=(int)(r0/NSQ),rem=(int)(r0%NSQ),iI=rem/NN,j0=rem%NN;
            const float* Pr=lng+(size_t)(bb*NN+iI)*128;
            #pragma unroll
            for(int ni=0;ni<4;ni++){
                int col=wc*32+ni*8+(lane&3)*2;
                int kp=col>>1;
                float2 p2=*(const float2*)(Pr+col);
                float2 b2=*(const float2*)(bias+col);
                #pragma unroll
                for(int mi=0;mi<2;mi++){
                    int rl=wr*32+mi*16+(lane>>2);
                    #pragma unroll
                    for(int h=0;h<2;h++){
                        int row=rl+h*8;
                        float2 c=*(float2*)&acc[mi][ni][h*2];
                        float2 q2=*(const float2*)(lnb+((size_t)(bb*NN+j0+row))*128+col);
                        float2 a2=*(const float2*)(add1+((size_t)r0+row)*128+col);
                        float ox=geluf(c.x+b2.x+p2.x+q2.x+a2.x);
                        float oy=geluf(c.y+b2.y+p2.y+q2.y+a2.y);
                        uint32_t hh,ll;split2(ox,oy,hh,ll);
                        sdst[((size_t)r0+row)*128+kp]=hh;
                        sdst[((size_t)r0+row)*128+64+kp]=ll;
                    }
                }
            }
        }else{ // 4,5 staged LN (4 threads per row)
            int m=tid>>2,qt=tid&3;
            size_t row=r0+m;
            const float* srow=stage+m*132+qt*32;
            float* orow=out+row*(size_t)o_st+o_cf+qt*32;
            const float* a1=add1+row*128+qt*32;
            const float* bi=bias+qt*32;
            float v[32];
            float s=0.f;
            #pragma unroll
            for(int n=0;n<32;n+=4){
                float4 c=*(const float4*)(srow+n);
                float4 a4=*(const float4*)(a1+n),b4=*(const float4*)(bi+n);
                v[n]=c.x+b4.x+a4.x;v[n+1]=c.y+b4.y+a4.y;
                v[n+2]=c.z+b4.z+a4.z;v[n+3]=c.w+b4.w+a4.w;
                if constexpr(MODE==4){
                    float4 t4=*(const float4*)(orow+n);
                    v[n]+=t4.x;v[n+1]+=t4.y;v[n+2]+=t4.z;v[n+3]+=t4.w;
                }
                s+=v[n]+v[n+1]+v[n+2]+v[n+3];
            }
            s+=__shfl_xor_sync(0xffffffffu,s,1);
            s+=__shfl_xor_sync(0xffffffffu,s,2);
            float mean=s*(1.f/128.f),s2=0.f;
            #pragma unroll
            for(int n=0;n<32;n++){v[n]-=mean;s2+=v[n]*v[n];}
            s2+=__shfl_xor_sync(0xffffffffu,s2,1);
            s2+=__shfl_xor_sync(0xffffffffu,s2,2);
            float rs=rsqrtf(s2*(1.f/128.f)+1e-5f);
            const float* gg=lng+qt*32;const float* bb2=lnb+qt*32;
            #pragma unroll
            for(int n=0;n<32;n+=4){
                float4 g4=*(const float4*)(gg+n),b4=*(const float4*)(bb2+n);
                float4 o;
                o.x=v[n]*rs*g4.x+b4.x;o.y=v[n+1]*rs*g4.y+b4.y;
                o.z=v[n+2]*rs*g4.z+b4.z;o.w=v[n+3]*rs*g4.w+b4.w;
                *(float4*)(orow+n)=o;
                if constexpr(MODE==5){
                    uint32_t h0,l0,h1,l1;
                    split2(o.x,o.y,h0,l0);split2(o.z,o.w,h1,l1);
                    int kp=qt*16+(n>>1);
                    uint32_t* dh=sdst+row*128+kp;
                    *(uint2*)dh=make_uint2(h0,h1);
                    *(uint2*)(dh+64)=make_uint2(l0,l1);
                }
            }
        }
        __syncthreads();
    }
}

// ===================== fused GEMM (N=256, 512 thr, R10 tiles: warp 32x64 via 2 B sets) =====================
// MODE: 0=RAW fp32, 3=GELU + split out (stride 256 u32)
template<int MODE>
__global__ __launch_bounds__(512,1) void k_mm2(
    const uint32_t* __restrict__ A,int a_st,
    const float* __restrict__ W,int w_ld,int w_cf,
    float* __restrict__ out,int o_st,int o_cf)
{
    extern __shared__ char dyn[];
    char* base=(char*)((((uintptr_t)dyn)+1023)&~(uintptr_t)1023);
    char* Ah=base;char* Al=base+32768;
    char* Wb[4]={base+65536,base+98304,base+131072,base+163840};
    int tid=threadIdx.x,wp=tid>>5,lane=tid&31;
    int wr=wp>>2,wc=wp&3;
    int l15=lane&15,kh=lane>>4,x7=l15&7;

    {   // weights for two N-128 sets (512 thr: nb from tid>>8? use n2 scheme from R10)
        int n2=tid&255,nb=n2>>7,n=n2&127,kq=(tid>>8)*64;
        char* rh=Wb[nb*2]+n*256;char* rl=Wb[nb*2+1]+n*256;
        int nx7=n&7;
        #pragma unroll
        for(int kk=0;kk<64;kk+=2){
            int k=kq+kk;
            float w0=__ldg(W+(size_t)k*w_ld+w_cf+nb*128+n);
            float w1=__ldg(W+(size_t)(k+1)*w_ld+w_cf+nb*128+n);
            uint32_t h2,l2;split2(w0,w1,h2,l2);
            int kp=k>>1;
            uint32_t s=(uint32_t)((((kp>>2)^nx7)<<4)+((kp&3)<<2));
            *(uint32_t*)(rh+s)=h2;*(uint32_t*)(rl+s)=l2;
        }
    }
    size_t t=blockIdx.x;
    if(t<T128)convCopy<false>(A,a_st,0,t,Ah,Al,tid);
    __syncthreads();
    uint32_t AhU=smem_u32(Ah),AlU=smem_u32(Al);
    uint32_t WhU[2]={smem_u32(Wb[0]),smem_u32(Wb[2])};
    uint32_t WlU[2]={smem_u32(Wb[1]),smem_u32(Wb[3])};
    uint32_t rowA0=(uint32_t)(wr*32+l15)*256,rowA1=(uint32_t)(wr*32+16+l15)*256;
    uint32_t rowB0=(uint32_t)(wc*32+l15)*256,rowB1=(uint32_t)(wc*32+16+l15)*256;

    for(;t<T128;t+=gridDim.x){
        float acc[2][2][4][4];
        #pragma unroll
        for(int nb=0;nb<2;nb++)
            #pragma unroll
            for(int mi=0;mi<2;mi++)
                #pragma unroll
                for(int ni=0;ni<4;ni++){acc[nb][mi][ni][0]=0.f;acc[nb][mi][ni][1]=0.f;acc[nb][mi][ni][2]=0.f;acc[nb][mi][ni][3]=0.f;}
        for(int ks=0;ks<8;ks++){
            uint32_t coff=(uint32_t)(((ks*2+kh)^x7)<<4);
            uint32_t ah[2][4],al[2][4];
            ldsm4(ah[0][0],ah[0][1],ah[0][2],ah[0][3],AhU+rowA0+coff);
            ldsm4(ah[1][0],ah[1][1],ah[1][2],ah[1][3],AhU+rowA1+coff);
            ldsm4(al[0][0],al[0][1],al[0][2],al[0][3],AlU+rowA0+coff);
            ldsm4(al[1][0],al[1][1],al[1][2],al[1][3],AlU+rowA1+coff);
            #pragma unroll
            for(int nb=0;nb<2;nb++){
                uint32_t bh0,bh1,bh2,bh3,bl0,bl1,bl2,bl3;
                ldsm4(bh0,bh1,bh2,bh3,WhU[nb]+rowB0+coff);
                ldsm4(bl0,bl1,bl2,bl3,WlU[nb]+rowB0+coff);
                #pragma unroll
                for(int mi=0;mi<2;mi++){
                    mma16816(acc[nb][mi][0],ah[mi],bh0,bh2);mma16816(acc[nb][mi][0],al[mi],bh0,bh2);mma16816(acc[nb][mi][0],ah[mi],bl0,bl2);
                    mma16816(acc[nb][mi][1],ah[mi],bh1,bh3);mma16816(acc[nb][mi][1],al[mi],bh1,bh3);mma16816(acc[nb][mi][1],ah[mi],bl1,bl3);
                }
                ldsm4(bh0,bh1,bh2,bh3,WhU[nb]+rowB1+coff);
                ldsm4(bl0,bl1,bl2,bl3,WlU[nb]+rowB1+coff);
                #pragma unroll
                for(int mi=0;mi<2;mi++){
                    mma16816(acc[nb][mi][2],ah[mi],bh0,bh2);mma16816(acc[nb][mi][2],al[mi],bh0,bh2);mma16816(acc[nb][mi][2],ah[mi],bl0,bl2);
                    mma16816(acc[nb][mi][3],ah[mi],bh1,bh3);mma16816(acc[nb][mi][3],al[mi],bh1,bh3);mma16816(acc[nb][mi][3],ah[mi],bl1,bl3);
                }
            }
        }
        __syncthreads();
        size_t tn=t+gridDim.x;
        if(tn<T128)convCopy<false>(A,a_st,0,tn,Ah,Al,tid);
        size_t r0=t*128;
        if constexpr(MODE==0){
            #pragma unroll
            for(int nb=0;nb<2;nb++){
                #pragma unroll
                for(int ni=0;ni<4;ni++){
                    int col=o_cf+nb*128+wc*32+ni*8+(lane&3)*2;
                    #pragma unroll
                    for(int mi=0;mi<2;mi++){
                        int rl=wr*32+mi*16+(lane>>2);
                        *(float2*)(out+((size_t)r0+rl)*o_st+col)=*(float2*)&acc[nb][mi][ni][0];
                        *(float2*)(out+((size_t)r0+rl+8)*o_st+col)=*(float2*)&acc[nb][mi][ni][2];
                    }
                }
            }
        }else{
            uint32_t* outu=(uint32_t*)out;
            #pragma unroll
            for(int nb=0;nb<2;nb++){
                #pragma unroll
                for(int ni=0;ni<4;ni++){
                    int kp=nb*64+wc*16+ni*4+(lane&3);
                    #pragma unroll
                    for(int mi=0;mi<2;mi++){
                        int rl=wr*32+mi*16+(lane>>2);
                        float a0=geluf(acc[nb][mi][ni][0]),a1=geluf(acc[nb][mi][ni][1]);
                        float a2=geluf(acc[nb][mi][ni][2]),a3=geluf(acc[nb][mi][ni][3]);
                        uint32_t h0,l0,h1,l1;
                        split2(a0,a1,h0,l0);split2(a2,a3,h1,l1);
                        outu[((size_t)r0+rl)*256+kp]=h0;outu[((size_t)r0+rl)*256+128+kp]=l0;
                        outu[((size_t)r0+rl+8)*256+kp]=h1;outu[((size_t)r0+rl+8)*256+128+kp]=l1;
                    }
                }
            }
        }
        __syncthreads();
    }
}

// ===================== small fp32 kernels =====================
__global__ __launch_bounds__(384) void k_qkvn(const float* __restrict__ node,const float* __restrict__ W){
    int row=blockIdx.x,c=threadIdx.x;
    __shared__ float s[DD];
    if(c<DD)s[c]=node[row*DD+c];
    __syncthreads();
    float a=0.f;
    #pragma unroll 8
    for(int k=0;k<DD;k++)a+=s[k]*W[k*384+c];
    g_qkvn[row*384+c]=a;
}

__global__ __launch_bounds__(128) void k_attn(){
    int w=threadIdx.x>>5,lane=threadIdx.x&31;
    int gw=blockIdx.x*4+w;
    int b=gw/(8*NN),rr=gw%(8*NN),h=rr/NN,i=rr%NN;
    const float* qb=g_qkvn+(b*NN+i)*384+h*48;
    float qv[16];
    #pragma unroll
    for(int c=0;c<16;c++)qv[c]=qb[c];
    const float* eb=g_qkve+((size_t)(b*NN+i)*NN)*512+h*64;
    float dl[12];
    #pragma unroll
    for(int t=0;t<12;t++){
        int j=lane+32*t;
        const float4* e4=(const float4*)(eb+(size_t)j*512);
        const float4* k4=(const float4*)(g_qkvn+(b*NN+j)*384+h*48+16);
        float d=0.f;
        #pragma unroll
        for(int q=0;q<4;q++){
            float4 eq=e4[q],ek=e4[4+q],kk=k4[q];
            d+=(qv[4*q]+eq.x)*(kk.x+ek.x)+(qv[4*q+1]+eq.y)*(kk.y+ek.y)
              +(qv[4*q+2]+eq.z)*(kk.z+ek.z)+(qv[4*q+3]+eq.w)*(kk.w+ek.w);
        }
        dl[t]=d*SCALE;
    }
    float m=dl[0];
    #pragma unroll
    for(int t=1;t<12;t++)m=fmaxf(m,dl[t]);
    m=wmax(m);
    float s=0.f,out[16];
    #pragma unroll
    for(int c=0;c<16;c++)out[c]=0.f;
    #pragma unroll
    for(int t=0;t<12;t++){
        int j=lane+32*t;
        float p=__expf(dl[t]-m);s+=p;
        const float4* e4=(const float4*)(eb+(size_t)j*512);
        const float4* v4=(const float4*)(g_qkvn+(b*NN+j)*384+h*48+32);
        #pragma unroll
        for(int q=0;q<4;q++){
            float4 ev=e4[8+q],em=e4[12+q],vn=v4[q];
            out[4*q]+=p*(vn.x*em.x+ev.x);out[4*q+1]+=p*(vn.y*em.y+ev.y);
            out[4*q+2]+=p*(vn.z*em.z+ev.z);out[4*q+3]+=p*(vn.w*em.w+ev.w);
        }
    }
    s=wsum(s);
    float inv=1.f/s;
    #pragma unroll
    for(int c=0;c<16;c++){
        float v=wsum(out[c]);
        if(lane==0)g_attn[(b*NN+i)*DD+h*16+c]=v*inv;
    }
}

__global__ __launch_bounds__(128) void k_node(const float* __restrict__ node,const float* __restrict__ w0,const float* __restrict__ b0,
    const float* __restrict__ g0,const float* __restrict__ be0,const float* __restrict__ g1,const float* __restrict__ be1,
    const float* __restrict__ w1,const float* __restrict__ w2,const float* __restrict__ b2,float* __restrict__ x){
    int row=blockIdx.x,c=threadIdx.x;
    __shared__ float sa[DD],sx[DD],sh[256],sr[8];
    sa[c]=g_attn[row*DD+c];
    __syncthreads();
    float y=b0[c];
    #pragma unroll 4
    for(int k=0;k<DD;k++)y+=sa[k]*w0[k*DD+c];
    float r=node[row*DD+c]+y;
    float t=wsum(r);if((c&31)==0)sr[c>>5]=t;__syncthreads();
    float mean=(sr[0]+sr[1]+sr[2]+sr[3])*(1.f/DD);
    float d=r-mean;
    t=wsum(d*d);if((c&31)==0)sr[4+(c>>5)]=t;__syncthreads();
    float x0=d*rsqrtf((sr[4]+sr[5]+sr[6]+sr[7])*(1.f/DD)+1e-5f)*g0[c]+be0[c];
    sx[c]=x0;__syncthreads();
    float h0=0.f,h1=0.f;
    #pragma unroll 4
    for(int k=0;k<DD;k++){float v=sx[k];h0+=v*w1[k*256+c];h1+=v*w1[k*256+c+128];}
    sh[c]=geluf(h0);sh[c+128]=geluf(h1);
    __syncthreads();
    float z=b2[c];
    #pragma unroll 4
    for(int k=0;k<256;k++)z+=sh[k]*w2[k*DD+c];
    float r2=x0+z;
    __syncthreads();
    t=wsum(r2);if((c&31)==0)sr[c>>5]=t;__syncthreads();
    float m2=(sr[0]+sr[1]+sr[2]+sr[3])*(1.f/DD);
    float d2=r2-m2;
    t=wsum(d2*d2);if((c&31)==0)sr[4+(c>>5)]=t;__syncthreads();
    x[row*DD+c]=d2*rsqrtf((sr[4]+sr[5]+sr[6]+sr[7])*(1.f/DD)+1e-5f)*g1[c]+be1[c];
}

__global__ __launch_bounds__(128) void k_means(const float* __restrict__ edge){
    int bi=blockIdx.x,c=threadIdx.x,b=bi/NN,r=bi%NN;
    float s=0.f;
    if(blockIdx.y==0){
        const float* p=edge+((size_t)(b*NN+r)*NN)*DD+c;
        for(int j=0;j<NN;j++)s+=p[(size_t)j*DD];
        g_mJ[bi*DD+c]=s*(1.f/NN);
    }else{
        const float* p=edge+((size_t)b*NSQ+r)*DD+c;
        for(int i=0;i<NN;i++)s+=p[(size_t)i*NN*DD];
        g_mI[bi*DD+c]=s*(1.f/NN);
    }
}

__global__ __launch_bounds__(128) void k_PQ(const float* __restrict__ x,const float* __restrict__ ws,const float* __restrict__ bs,
    const float* __restrict__ wt,const float* __restrict__ bt,const float* __restrict__ wer,const float* __restrict__ wec){
    int bi=blockIdx.x,c=threadIdx.x;
    __shared__ float sx[DD],sj[DD],si[DD];
    sx[c]=x[bi*DD+c];sj[c]=g_mJ[bi*DD+c];si[c]=g_mI[bi*DD+c];
    __syncthreads();
    float P=bs[c],Q=bt[c];
    #pragma unroll 4
    for(int k=0;k<DD;k++){
        P+=sx[k]*ws[k*DD+c]+sj[k]*wer[k*DD+c];
        Q+=sx[k]*wt[k*DD+c]+si[k]*wec[k*DD+c];
    }
    g_P[bi*DD+c]=P;g_Q[bi*DD+c]=Q;
}

extern "C" void kernel_launch(void* const* d_in,const int* in_sizes,int n_in,void* d_out,int out_size){
    const float* node=(const float*)d_in[0];
    const float* edge=(const float*)d_in[1];
    const float* wqkvn=(const float*)d_in[3];
    const float* wqkve=(const float*)d_in[4];
    const float* lin0w=(const float*)d_in[5];
    const float* lin0b=(const float*)d_in[6];
    const float* ln0g=(const float*)d_in[7];
    const float* ln0b=(const float*)d_in[8];
    const float* ln1g=(const float*)d_in[9];
    const float* ln1b=(const float*)d_in[10];
    const float* w1=(const float*)d_in[11];
    const float* w2=(const float*)d_in[12];
    const float* b2=(const float*)d_in[13];
    const float* e0we=(const float*)d_in[14];
    const float* e0be=(const float*)d_in[15];
    const float* e0ws=(const float*)d_in[16];
    const float* e0bs=(const float*)d_in[17];
    const float* e0wt=(const float*)d_in[18];
    const float* e0bt=(const float*)d_in[19];
    const float* e0wer=(const float*)d_in[20];
    const float* e0wec=(const float*)d_in[21];
    const float* e0w1=(const float*)d_in[22];
    const float* e0b1=(const float*)d_in[23];
    const float* e1w1=(const float*)d_in[24];
    const float* e1w2=(const float*)d_in[25];
    const float* e1b2=(const float*)d_in[26];
    const float* eln0g=(const float*)d_in[27];
    const float* eln0b=(const float*)d_in[28];
    const float* eln1g=(const float*)d_in[29];
    const float* eln1b=(const float*)d_in[30];
    float* xout=(float*)d_out;
    float* eout=(float*)d_out+(size_t)ROWS_N*DD;

    const int SM_SMALL=131072+1024;
    const int SM_STAGE=131072+132*128*4+1024;
    const int SM_BIG=196608+1024;
    cudaFuncSetAttribute((const void*)k_mm<0,false>,cudaFuncAttributeMaxDynamicSharedMemorySize,SM_SMALL);
    cudaFuncSetAttribute((const void*)k_mm<1,true >,cudaFuncAttributeMaxDynamicSharedMemorySize,SM_SMALL);
    cudaFuncSetAttribute((const void*)k_mm<4,false>,cudaFuncAttributeMaxDynamicSharedMemorySize,SM_STAGE);
    cudaFuncSetAttribute((const void*)k_mm<5,false>,cudaFuncAttributeMaxDynamicSharedMemorySize,SM_STAGE);
    cudaFuncSetAttribute((const void*)k_mm2<0>,cudaFuncAttributeMaxDynamicSharedMemorySize,SM_BIG);
    cudaFuncSetAttribute((const void*)k_mm2<3>,cudaFuncAttributeMaxDynamicSharedMemorySize,SM_BIG);

    float *gq,*gh,*gb;
    cudaGetSymbolAddress((void**)&gq,g_qkve);
    cudaGetSymbolAddress((void**)&gh,g_h);
    cudaGetSymbolAddress((void**)&gb,g_buf);
    uint32_t* se=(uint32_t*)gh;                          // split-edge (g_h phase 1)
    float* gqs=gq;                                       // e1 pass1 fp32 scratch (g_qkve, post-attn)
    uint32_t* seo=(uint32_t*)gq+(size_t)ROWS_E*128;      // split eout (disjoint quarter of g_qkve)
    uint32_t* sbuf=(uint32_t*)gb;                        // split e1-out (g_buf phase 1)
    uint32_t* shh=(uint32_t*)gh;                         // split h (g_h phase 2)

    k_qkvn<<<ROWS_N,384>>>(node,wqkvn);
    k_split_edge<<<ROWS_E*2/256,256>>>(edge,se);
    for(int q=0;q<2;q++)
        k_mm2<0><<<148,512,SM_BIG>>>(se,128, wqkve,512,q*256, gq,512,q*256);
    k_means<<<dim3(ROWS_N,2),128>>>(edge);
    k_attn<<<ROWS_N*8/4,128>>>();
    k_node<<<ROWS_N,128>>>(node,lin0w,lin0b,ln0g,ln0b,ln1g,ln1b,w1,w2,b2,xout);
    k_PQ<<<ROWS_N,128>>>(xout,e0ws,e0bs,e0wt,e0bt,e0wer,e0wec);
    // e1 pass1: se @ We[0:128] -> gqs fp32 (stride 128) [g_qkve free after attn]
    k_mm<0,false><<<148,512,SM_SMALL>>>(se,128,0, e0we,128,0, gqs,128,0, nullptr,nullptr,nullptr,nullptr,nullptr);
    // e1 pass2: seT @ We[128:256] + gqs + be + P + Q -> gelu -> split g_buf
    float *gp,*gqq2;
    cudaGetSymbolAddress((void**)&gp,g_P);
    cudaGetSymbolAddress((void**)&gqq2,g_Q);
    k_mm<1,true ><<<148,512,SM_SMALL>>>(se,128,0, e0we+(size_t)128*128,128,0, nullptr,0,0, gqs,e0be,gp,gqq2, sbuf);
    // e2: LN(edge + e1@W1 + b1) -> eout fp32 + split copy -> seo
    k_mm<5,false><<<148,512,SM_STAGE>>>(sbuf,128,0, e0w1,128,0, eout,128,0, edge,e0b1,eln0g,eln0b, seo);
    // e3: h = gelu(eout @ e1w1), N=256 -> split g_h (stride 256) [se dead after e1]
    k_mm2<3><<<148,512,SM_BIG>>>(seo,128, e1w1,256,0, gh,256,0);
    // e4 pass1: h[:,0:128] @ W2[0:128] -> g_buf fp32 scratch [sbuf dead after e2]
    k_mm<0,false><<<148,512,SM_SMALL>>>(shh,256,0, e1w2,128,0, gb,128,0, nullptr,nullptr,nullptr,nullptr,nullptr);
    // e4 pass2: LN(eout + scratch + h[:,128:256]@W2[128:256] + b2) -> eout
    k_mm<4,false><<<148,512,SM_STAGE>>>(shh,256,64, e1w2+(size_t)128*128,128,0, eout,128,0, gb,e1b2,eln1g,eln1b, nullptr);
}

// round 16
// speedup vs baseline: 1.7921x; 1.6433x over previous
#include <cuda_runtime.h>
#include <math.h>
#include <stdint.h>

#define NB 2
#define NN 384
#define DD 128
#define NSQ (NN*NN)
#define ROWS_E (NB*NSQ)
#define ROWS_N (NB*NN)
#define T128 (ROWS_E/128)    // 2304
#define SCALE 0.08838834764831845f

__device__ __align__(256) float g_qkvn[ROWS_N*384];
__device__ __align__(256) uint32_t g_qkvb[(size_t)ROWS_E*256];   // bf16 qkve (302MB)
__device__ __align__(256) float g_attn[ROWS_N*DD];
__device__ __align__(256) float g_mJ[ROWS_N*DD];
__device__ __align__(256) float g_mI[ROWS_N*DD];
__device__ __align__(256) float g_P[ROWS_N*DD];
__device__ __align__(256) float g_Q[ROWS_N*DD];
__device__ __align__(256) float g_buf[(size_t)ROWS_E*DD];
__device__ __align__(256) float g_s1[(size_t)ROWS_E*DD];         // fp32 scratch
__device__ __align__(256) uint32_t g_hb[(size_t)ROWS_E*128];     // bf16 h (151MB)

__device__ __forceinline__ float geluf(float x){return 0.5f*x*(1.f+erff(x*0.70710678118654752f));}
__device__ __forceinline__ float wsum(float v){
    #pragma unroll
    for(int o=16;o;o>>=1)v+=__shfl_xor_sync(0xffffffffu,v,o);return v;}
__device__ __forceinline__ float wmax(float v){
    #pragma unroll
    for(int o=16;o;o>>=1)v=fmaxf(v,__shfl_xor_sync(0xffffffffu,v,o));return v;}
__device__ __forceinline__ float uaf(uint32_t u){return __uint_as_float(u);}
__device__ __forceinline__ float2 upbf(uint32_t u){return make_float2(uaf(u<<16),uaf(u&0xffff0000u));}
__device__ __forceinline__ uint32_t pkbf(float a,float b){uint32_t r;asm("cvt.rn.bf16x2.f32 %0,%1,%2;":"=r"(r):"f"(b),"f"(a));return r;}

__device__ __forceinline__ uint32_t smem_u32(const void* p){
    uint32_t a;asm("{ .reg .u64 t; cvta.to.shared.u64 t, %1; cvt.u32.u64 %0, t; }":"=r"(a):"l"(p));return a;}
__device__ __forceinline__ void split2(float a,float b,uint32_t&h,uint32_t&l){
    asm("cvt.rn.bf16x2.f32 %0,%1,%2;":"=r"(h):"f"(b),"f"(a));
    float ha=__uint_as_float(h<<16),hb=__uint_as_float(h&0xffff0000u);
    float la=a-ha,lb=b-hb;
    asm("cvt.rn.bf16x2.f32 %0,%1,%2;":"=r"(l):"f"(lb),"f"(la));}
__device__ __forceinline__ void ldsm4(uint32_t&r0,uint32_t&r1,uint32_t&r2,uint32_t&r3,uint32_t a){
    asm volatile("ldmatrix.sync.aligned.m8n8.x4.shared.b16 {%0,%1,%2,%3},[%4];"
        :"=r"(r0),"=r"(r1),"=r"(r2),"=r"(r3):"r"(a));}
__device__ __forceinline__ void mma16816(float* d,const uint32_t* a,uint32_t b0,uint32_t b1){
    asm volatile("mma.sync.aligned.m16n8k16.row.col.f32.bf16.bf16.f32 "
        "{%0,%1,%2,%3},{%4,%5,%6,%7},{%8,%9},{%0,%1,%2,%3};"
        :"+f"(d[0]),"+f"(d[1]),"+f"(d[2]),"+f"(d[3])
        :"r"(a[0]),"r"(a[1]),"r"(a[2]),"r"(a[3]),"r"(b0),"r"(b1));}

// fp32 tile -> hi/lo bf16 smem (R10 convA; 512 thr, 4/row)
template<bool TRANS>
__device__ __forceinline__ void convA(const float* __restrict__ A,int a_s4,int a_c4,
                                      size_t t,char* hi,char* lo,int tid){
    size_t r0=t*128;
    int m=tid>>2,qt=tid&3;
    const float4* src;
    if(TRANS){
        int bb=(int)(r0/NSQ),rem=(int)(r0%NSQ),iI=rem/NN,j0=rem%NN;
        src=(const float4*)A+((size_t)(bb*NN+(j0+m))*NN+iI)*32+qt*8;
    }else{
        src=(const float4*)A+(r0+m)*(size_t)a_s4+a_c4+qt*8;
    }
    char* rh=hi+m*256;char* rl=lo+m*256;
    int x7=m&7;
    #pragma unroll
    for(int i=0;i<8;i++){
        float4 x=__ldg(src+i);
        uint32_t h0,l0,h1,l1;
        split2(x.x,x.y,h0,l0);split2(x.z,x.w,h1,l1);
        int ig=qt*8+i;
        int kp0=ig*2,kp1=ig*2+1;
        uint32_t s0=(uint32_t)((((kp0>>2)^x7)<<4)+((kp0&3)<<2));
        uint32_t s1=(uint32_t)((((kp1>>2)^x7)<<4)+((kp1&3)<<2));
        *(uint32_t*)(rh+s0)=h0;*(uint32_t*)(rh+s1)=h1;
        *(uint32_t*)(rl+s0)=l0;*(uint32_t*)(rl+s1)=l1;
    }
}
// bf16 tile copy loader (rows of a_s4 uint4; chunk offset a_c4 uint4)
__device__ __forceinline__ void convB16(const uint32_t* __restrict__ A,int a_s4,int a_c4,
                                        size_t t,char* hi,int tid){
    size_t r0=t*128;
    int m=tid>>2,q=tid&3,x7=m&7;
    const uint4* src=(const uint4*)A+(r0+m)*(size_t)a_s4+a_c4+q*4;
    char* rh=hi+m*256;
    #pragma unroll
    for(int i=0;i<4;i++){
        int g=q*4+i;
        *(uint4*)(rh+((g^x7)<<4))=__ldg(src+i);
    }
}

// ===================== unfused GEMM (N=128, 512 thr, warp 32x32) =====================
// MODE: 0=RAW fp32, 1=E1 gelu(c+b+add1+P+Q) fp32, 2=LN(c+b+add1) staged, 4=LN(c+b+add1+out) staged
template<int MODE,bool TRANS,bool AB16>
__global__ __launch_bounds__(512,1) void k_mm(
    const float* __restrict__ A,int a_s4,int a_c4,
    const float* __restrict__ W,int w_ld,int w_cf,
    float* __restrict__ out,int o_st,int o_cf,
    const float* __restrict__ add1,const float* __restrict__ bias,
    const float* __restrict__ lng,const float* __restrict__ lnb)
{
    extern __shared__ char dyn[];
    char* base=(char*)((((uintptr_t)dyn)+1023)&~(uintptr_t)1023);
    char* Ah=base;
    char* Al=AB16?nullptr:base+32768;
    char* Wh=AB16?base+32768:base+65536;
    char* Wl=Wh+32768;
    float* stage=(float*)(Wl+32768);
    int tid=threadIdx.x,wp=tid>>5,lane=tid&31;
    int wr=wp>>2,wc=wp&3;
    int l15=lane&15,kh=lane>>4,x7=l15&7;

    {   // weights (hi/lo split)
        int n=tid&127,kq=(tid>>7)*32;
        char* rh=Wh+n*256;char* rl=Wl+n*256;
        int nx7=n&7;
        #pragma unroll
        for(int kk=0;kk<32;kk+=2){
            int k=kq+kk;
            float w0=__ldg(W+(size_t)k*w_ld+w_cf+n);
            float w1=__ldg(W+(size_t)(k+1)*w_ld+w_cf+n);
            uint32_t h2,l2;split2(w0,w1,h2,l2);
            int kp=k>>1;
            uint32_t s=(uint32_t)((((kp>>2)^nx7)<<4)+((kp&3)<<2));
            *(uint32_t*)(rh+s)=h2;*(uint32_t*)(rl+s)=l2;
        }
    }
    size_t t=blockIdx.x;
    if(t<T128){
        if(AB16)convB16((const uint32_t*)A,a_s4,a_c4,t,Ah,tid);
        else convA<TRANS>(A,a_s4,a_c4,t,Ah,Al,tid);
    }
    __syncthreads();
    uint32_t AhU=smem_u32(Ah),AlU=AB16?0:smem_u32(Al),WhU=smem_u32(Wh),WlU=smem_u32(Wl);
    uint32_t rowA0=(uint32_t)(wr*32+l15)*256,rowA1=(uint32_t)(wr*32+16+l15)*256;
    uint32_t rowB0=(uint32_t)(wc*32+l15)*256,rowB1=(uint32_t)(wc*32+16+l15)*256;

    for(;t<T128;t+=gridDim.x){
        float acc[2][4][4];
        #pragma unroll
        for(int mi=0;mi<2;mi++)
            #pragma unroll
            for(int ni=0;ni<4;ni++){acc[mi][ni][0]=0.f;acc[mi][ni][1]=0.f;acc[mi][ni][2]=0.f;acc[mi][ni][3]=0.f;}
        #pragma unroll 2
        for(int ks=0;ks<8;ks++){
            uint32_t coff=(uint32_t)(((ks*2+kh)^x7)<<4);
            uint32_t ah[2][4],al[2][4];
            ldsm4(ah[0][0],ah[0][1],ah[0][2],ah[0][3],AhU+rowA0+coff);
            ldsm4(ah[1][0],ah[1][1],ah[1][2],ah[1][3],AhU+rowA1+coff);
            if(!AB16){
                ldsm4(al[0][0],al[0][1],al[0][2],al[0][3],AlU+rowA0+coff);
                ldsm4(al[1][0],al[1][1],al[1][2],al[1][3],AlU+rowA1+coff);
            }
            uint32_t bh0,bh1,bh2,bh3,bl0,bl1,bl2,bl3;
            ldsm4(bh0,bh1,bh2,bh3,WhU+rowB0+coff);
            ldsm4(bl0,bl1,bl2,bl3,WlU+rowB0+coff);
            #pragma unroll
            for(int mi=0;mi<2;mi++){
                mma16816(acc[mi][0],ah[mi],bh0,bh2);
                if(!AB16)mma16816(acc[mi][0],al[mi],bh0,bh2);
                mma16816(acc[mi][0],ah[mi],bl0,bl2);
                mma16816(acc[mi][1],ah[mi],bh1,bh3);
                if(!AB16)mma16816(acc[mi][1],al[mi],bh1,bh3);
                mma16816(acc[mi][1],ah[mi],bl1,bl3);
            }
            ldsm4(bh0,bh1,bh2,bh3,WhU+rowB1+coff);
            ldsm4(bl0,bl1,bl2,bl3,WlU+rowB1+coff);
            #pragma unroll
            for(int mi=0;mi<2;mi++){
                mma16816(acc[mi][2],ah[mi],bh0,bh2);
                if(!AB16)mma16816(acc[mi][2],al[mi],bh0,bh2);
                mma16816(acc[mi][2],ah[mi],bl0,bl2);
                mma16816(acc[mi][3],ah[mi],bh1,bh3);
                if(!AB16)mma16816(acc[mi][3],al[mi],bh1,bh3);
                mma16816(acc[mi][3],ah[mi],bl1,bl3);
            }
        }
        size_t r0=t*128;
        if constexpr(MODE==2||MODE==4){
            #pragma unroll
            for(int mi=0;mi<2;mi++){
                int row=wr*32+mi*16+(lane>>2);
                #pragma unroll
                for(int ni=0;ni<4;ni++){
                    int col=wc*32+ni*8+(lane&3)*2;
                    *(float2*)&stage[row*132+col]=make_float2(acc[mi][ni][0],acc[mi][ni][1]);
                    *(float2*)&stage[(row+8)*132+col]=make_float2(acc[mi][ni][2],acc[mi][ni][3]);
                }
            }
        }
        __syncthreads();
        size_t tn=t+gridDim.x;
        if(tn<T128){
            if(AB16)convB16((const uint32_t*)A,a_s4,a_c4,tn,Ah,tid);
            else convA<TRANS>(A,a_s4,a_c4,tn,Ah,Al,tid);
        }
        if constexpr(MODE==0){
            #pragma unroll
            for(int ni=0;ni<4;ni++){
                int col=o_cf+wc*32+ni*8+(lane&3)*2;
                #pragma unroll
                for(int mi=0;mi<2;mi++){
                    int rl=wr*32+mi*16+(lane>>2);
                    *(float2*)(out+((size_t)r0+rl)*o_st+col)=*(float2*)&acc[mi][ni][0];
                    *(float2*)(out+((size_t)r0+rl+8)*o_st+col)=*(float2*)&acc[mi][ni][2];
                }
            }
        }else if constexpr(MODE==1){
            int bb=(int)(r0/NSQ),rem=(int)(r0%NSQ),iI=rem/NN,j0=rem%NN;
            const float* Pr=lng+(size_t)(bb*NN+iI)*128;
            #pragma unroll
            for(int ni=0;ni<4;ni++){
                int col=wc*32+ni*8+(lane&3)*2;
                float2 p2=*(const float2*)(Pr+col);
                float2 b2=*(const float2*)(bias+col);
                #pragma unroll
                for(int mi=0;mi<2;mi++){
                    int rl=wr*32+mi*16+(lane>>2);
                    #pragma unroll
                    for(int h=0;h<2;h++){
                        int row=rl+h*8;
                        float2 c=*(float2*)&acc[mi][ni][h*2];
                        float2 q2=*(const float2*)(lnb+((size_t)(bb*NN+j0+row))*128+col);
                        float2 a2=*(const float2*)(add1+((size_t)r0+row)*128+col);
                        float2 o;
                        o.x=geluf(c.x+b2.x+p2.x+q2.x+a2.x);
                        o.y=geluf(c.y+b2.y+p2.y+q2.y+a2.y);
                        *(float2*)(out+((size_t)r0+row)*o_st+o_cf+col)=o;
                    }
                }
            }
        }else{
            int m=tid>>2,qt=tid&3;
            size_t row=r0+m;
            const float* srow=stage+m*132+qt*32;
            float* orow=out+row*(size_t)o_st+o_cf+qt*32;
            const float* a1=add1+row*128+qt*32;
            const float* bi=bias+qt*32;
            float v[32];
            float s=0.f;
            #pragma unroll
            for(int n=0;n<32;n+=4){
                float4 c=*(const float4*)(srow+n);
                float4 a4=*(const float4*)(a1+n),b4=*(const float4*)(bi+n);
                v[n]=c.x+b4.x+a4.x;v[n+1]=c.y+b4.y+a4.y;
                v[n+2]=c.z+b4.z+a4.z;v[n+3]=c.w+b4.w+a4.w;
                if constexpr(MODE==4){
                    float4 t4=*(const float4*)(orow+n);
                    v[n]+=t4.x;v[n+1]+=t4.y;v[n+2]+=t4.z;v[n+3]+=t4.w;
                }
                s+=v[n]+v[n+1]+v[n+2]+v[n+3];
            }
            s+=__shfl_xor_sync(0xffffffffu,s,1);
            s+=__shfl_xor_sync(0xffffffffu,s,2);
            float mean=s*(1.f/128.f),s2=0.f;
            #pragma unroll
            for(int n=0;n<32;n++){v[n]-=mean;s2+=v[n]*v[n];}
            s2+=__shfl_xor_sync(0xffffffffu,s2,1);
            s2+=__shfl_xor_sync(0xffffffffu,s2,2);
            float rs=rsqrtf(s2*(1.f/128.f)+1e-5f);
            const float* gg=lng+qt*32;const float* bb2=lnb+qt*32;
            #pragma unroll
            for(int n=0;n<32;n+=4){
                float4 g4=*(const float4*)(gg+n),b4=*(const float4*)(bb2+n);
                float4 o;
                o.x=v[n]*rs*g4.x+b4.x;o.y=v[n+1]*rs*g4.y+b4.y;
                o.z=v[n+2]*rs*g4.z+b4.z;o.w=v[n+3]*rs*g4.w+b4.w;
                *(float4*)(orow+n)=o;
            }
        }
        __syncthreads();
    }
}

// ===================== fused GEMM (N=256, 512 thr) -> bf16 out =====================
// MODE: 6=RAW bf16 pack, 7=GELU bf16 pack. out treated as u32*, o_stu u32 stride, o_cfu u32 col offset
template<int MODE>
__global__ __launch_bounds__(512,1) void k_mm2(
    const float* __restrict__ A,int a_s4,
    const float* __restrict__ W,int w_ld,int w_cf,
    uint32_t* __restrict__ outu,int o_stu,int o_cfu)
{
    extern __shared__ char dyn[];
    char* base=(char*)((((uintptr_t)dyn)+1023)&~(uintptr_t)1023);
    char* Ah=base;char* Al=base+32768;
    char* Wb[4]={base+65536,base+98304,base+131072,base+163840};
    int tid=threadIdx.x,wp=tid>>5,lane=tid&31;
    int wr=wp>>2,wc=wp&3;
    int l15=lane&15,kh=lane>>4,x7=l15&7;

    {
        int n2=tid&255,nb=n2>>7,n=n2&127,kq=(tid>>8)*64;
        char* rh=Wb[nb*2]+n*256;char* rl=Wb[nb*2+1]+n*256;
        int nx7=n&7;
        #pragma unroll
        for(int kk=0;kk<64;kk+=2){
            int k=kq+kk;
            float w0=__ldg(W+(size_t)k*w_ld+w_cf+nb*128+n);
            float w1=__ldg(W+(size_t)(k+1)*w_ld+w_cf+nb*128+n);
            uint32_t h2,l2;split2(w0,w1,h2,l2);
            int kp=k>>1;
            uint32_t s=(uint32_t)((((kp>>2)^nx7)<<4)+((kp&3)<<2));
            *(uint32_t*)(rh+s)=h2;*(uint32_t*)(rl+s)=l2;
        }
    }
    size_t t=blockIdx.x;
    if(t<T128)convA<false>(A,a_s4,0,t,Ah,Al,tid);
    __syncthreads();
    uint32_t AhU=smem_u32(Ah),AlU=smem_u32(Al);
    uint32_t WhU[2]={smem_u32(Wb[0]),smem_u32(Wb[2])};
    uint32_t WlU[2]={smem_u32(Wb[1]),smem_u32(Wb[3])};
    uint32_t rowA0=(uint32_t)(wr*32+l15)*256,rowA1=(uint32_t)(wr*32+16+l15)*256;
    uint32_t rowB0=(uint32_t)(wc*32+l15)*256,rowB1=(uint32_t)(wc*32+16+l15)*256;

    for(;t<T128;t+=gridDim.x){
        float acc[2][2][4][4];
        #pragma unroll
        for(int nb=0;nb<2;nb++)
            #pragma unroll
            for(int mi=0;mi<2;mi++)
                #pragma unroll
                for(int ni=0;ni<4;ni++){acc[nb][mi][ni][0]=0.f;acc[nb][mi][ni][1]=0.f;acc[nb][mi][ni][2]=0.f;acc[nb][mi][ni][3]=0.f;}
        for(int ks=0;ks<8;ks++){
            uint32_t coff=(uint32_t)(((ks*2+kh)^x7)<<4);
            uint32_t ah[2][4],al[2][4];
            ldsm4(ah[0][0],ah[0][1],ah[0][2],ah[0][3],AhU+rowA0+coff);
            ldsm4(ah[1][0],ah[1][1],ah[1][2],ah[1][3],AhU+rowA1+coff);
            ldsm4(al[0][0],al[0][1],al[0][2],al[0][3],AlU+rowA0+coff);
            ldsm4(al[1][0],al[1][1],al[1][2],al[1][3],AlU+rowA1+coff);
            #pragma unroll
            for(int nb=0;nb<2;nb++){
                uint32_t bh0,bh1,bh2,bh3,bl0,bl1,bl2,bl3;
                ldsm4(bh0,bh1,bh2,bh3,WhU[nb]+rowB0+coff);
                ldsm4(bl0,bl1,bl2,bl3,WlU[nb]+rowB0+coff);
                #pragma unroll
                for(int mi=0;mi<2;mi++){
                    mma16816(acc[nb][mi][0],ah[mi],bh0,bh2);mma16816(acc[nb][mi][0],al[mi],bh0,bh2);mma16816(acc[nb][mi][0],ah[mi],bl0,bl2);
                    mma16816(acc[nb][mi][1],ah[mi],bh1,bh3);mma16816(acc[nb][mi][1],al[mi],bh1,bh3);mma16816(acc[nb][mi][1],ah[mi],bl1,bl3);
                }
                ldsm4(bh0,bh1,bh2,bh3,WhU[nb]+rowB1+coff);
                ldsm4(bl0,bl1,bl2,bl3,WlU[nb]+rowB1+coff);
                #pragma unroll
                for(int mi=0;mi<2;mi++){
                    mma16816(acc[nb][mi][2],ah[mi],bh0,bh2);mma16816(acc[nb][mi][2],al[mi],bh0,bh2);mma16816(acc[nb][mi][2],ah[mi],bl0,bl2);
                    mma16816(acc[nb][mi][3],ah[mi],bh1,bh3);mma16816(acc[nb][mi][3],al[mi],bh1,bh3);mma16816(acc[nb][mi][3],ah[mi],bl1,bl3);
                }
            }
        }
        __syncthreads();
        size_t tn=t+gridDim.x;
        if(tn<T128)convA<false>(A,a_s4,0,tn,Ah,Al,tid);
        size_t r0=t*128;
        #pragma unroll
        for(int nb=0;nb<2;nb++){
            #pragma unroll
            for(int ni=0;ni<4;ni++){
                int kp=o_cfu+(nb*128+wc*32+ni*8+(lane&3)*2)/2;
                #pragma unroll
                for(int mi=0;mi<2;mi++){
                    int rl=wr*32+mi*16+(lane>>2);
                    float a0=acc[nb][mi][ni][0],a1=acc[nb][mi][ni][1];
                    float a2=acc[nb][mi][ni][2],a3=acc[nb][mi][ni][3];
                    if constexpr(MODE==7){a0=geluf(a0);a1=geluf(a1);a2=geluf(a2);a3=geluf(a3);}
                    outu[((size_t)r0+rl)*o_stu+kp]=pkbf(a0,a1);
                    outu[((size_t)r0+rl+8)*o_stu+kp]=pkbf(a2,a3);
                }
            }
        }
        __syncthreads();
    }
}

// ===================== small kernels =====================
__global__ __launch_bounds__(384) void k_qkvn(const float* __restrict__ node,const float* __restrict__ W){
    int row=blockIdx.x,c=threadIdx.x;
    __shared__ float s[DD];
    if(c<DD)s[c]=node[row*DD+c];
    __syncthreads();
    float a=0.f;
    #pragma unroll 8
    for(int k=0;k<DD;k++)a+=s[k]*W[k*384+c];
    g_qkvn[row*384+c]=a;
}

__global__ __launch_bounds__(128) void k_attn(){
    int w=threadIdx.x>>5,lane=threadIdx.x&31;
    int gw=blockIdx.x*4+w;
    int b=gw/(8*NN),rr=gw%(8*NN),h=rr/NN,i=rr%NN;
    const float* qb=g_qkvn+(b*NN+i)*384+h*48;
    float qv[16];
    #pragma unroll
    for(int c=0;c<16;c++)qv[c]=qb[c];
    const uint32_t* eb=g_qkvb+((size_t)(b*NN+i)*NN)*256+h*32;
    float dl[12];
    #pragma unroll
    for(int t=0;t<12;t++){
        int j=lane+32*t;
        const uint4* e4=(const uint4*)(eb+(size_t)j*256);
        uint32_t EQ[8],EK[8];
        *(uint4*)EQ=e4[0];*(uint4*)(EQ+4)=e4[1];
        *(uint4*)EK=e4[2];*(uint4*)(EK+4)=e4[3];
        const float* kn=g_qkvn+(b*NN+j)*384+h*48+16;
        float d=0.f;
        #pragma unroll
        for(int u=0;u<8;u++){
            float2 eq=upbf(EQ[u]),ek=upbf(EK[u]);
            d+=(qv[2*u]+eq.x)*(kn[2*u]+ek.x)+(qv[2*u+1]+eq.y)*(kn[2*u+1]+ek.y);
        }
        dl[t]=d*SCALE;
    }
    float m=dl[0];
    #pragma unroll
    for(int t=1;t<12;t++)m=fmaxf(m,dl[t]);
    m=wmax(m);
    float s=0.f,out[16];
    #pragma unroll
    for(int c=0;c<16;c++)out[c]=0.f;
    #pragma unroll
    for(int t=0;t<12;t++){
        int j=lane+32*t;
        float p=__expf(dl[t]-m);s+=p;
        const uint4* e4=(const uint4*)(eb+(size_t)j*256);
        uint32_t EV[8],EM[8];
        *(uint4*)EV=e4[4];*(uint4*)(EV+4)=e4[5];
        *(uint4*)EM=e4[6];*(uint4*)(EM+4)=e4[7];
        const float* vn=g_qkvn+(b*NN+j)*384+h*48+32;
        #pragma unroll
        for(int u=0;u<8;u++){
            float2 ev=upbf(EV[u]),em=upbf(EM[u]);
            out[2*u]+=p*(vn[2*u]*em.x+ev.x);
            out[2*u+1]+=p*(vn[2*u+1]*em.y+ev.y);
        }
    }
    s=wsum(s);
    float inv=1.f/s;
    #pragma unroll
    for(int c=0;c<16;c++){
        float v=wsum(out[c]);
        if(lane==0)g_attn[(b*NN+i)*DD+h*16+c]=v*inv;
    }
}

__global__ __launch_bounds__(128) void k_node(const float* __restrict__ node,const float* __restrict__ w0,const float* __restrict__ b0,
    const float* __restrict__ g0,const float* __restrict__ be0,const float* __restrict__ g1,const float* __restrict__ be1,
    const float* __restrict__ w1,const float* __restrict__ w2,const float* __restrict__ b2,float* __restrict__ x){
    int row=blockIdx.x,c=threadIdx.x;
    __shared__ float sa[DD],sx[DD],sh[256],sr[8];
    sa[c]=g_attn[row*DD+c];
    __syncthreads();
    float y=b0[c];
    #pragma unroll 4
    for(int k=0;k<DD;k++)y+=sa[k]*w0[k*DD+c];
    float r=node[row*DD+c]+y;
    float t=wsum(r);if((c&31)==0)sr[c>>5]=t;__syncthreads();
    float mean=(sr[0]+sr[1]+sr[2]+sr[3])*(1.f/DD);
    float d=r-mean;
    t=wsum(d*d);if((c&31)==0)sr[4+(c>>5)]=t;__syncthreads();
    float x0=d*rsqrtf((sr[4]+sr[5]+sr[6]+sr[7])*(1.f/DD)+1e-5f)*g0[c]+be0[c];
    sx[c]=x0;__syncthreads();
    float h0=0.f,h1=0.f;
    #pragma unroll 4
    for(int k=0;k<DD;k++){float v=sx[k];h0+=v*w1[k*256+c];h1+=v*w1[k*256+c+128];}
    sh[c]=geluf(h0);sh[c+128]=geluf(h1);
    __syncthreads();
    float z=b2[c];
    #pragma unroll 4
    for(int k=0;k<256;k++)z+=sh[k]*w2[k*DD+c];
    float r2=x0+z;
    __syncthreads();
    t=wsum(r2);if((c&31)==0)sr[c>>5]=t;__syncthreads();
    float m2=(sr[0]+sr[1]+sr[2]+sr[3])*(1.f/DD);
    float d2=r2-m2;
    t=wsum(d2*d2);if((c&31)==0)sr[4+(c>>5)]=t;__syncthreads();
    x[row*DD+c]=d2*rsqrtf((sr[4]+sr[5]+sr[6]+sr[7])*(1.f/DD)+1e-5f)*g1[c]+be1[c];
}

__global__ __launch_bounds__(128) void k_means(const float* __restrict__ edge){
    int bi=blockIdx.x,c=threadIdx.x,b=bi/NN,r=bi%NN;
    float s=0.f;
    if(blockIdx.y==0){
        const float* p=edge+((size_t)(b*NN+r)*NN)*DD+c;
        for(int j=0;j<NN;j++)s+=p[(size_t)j*DD];
        g_mJ[bi*DD+c]=s*(1.f/NN);
    }else{
        const float* p=edge+((size_t)b*NSQ+r)*DD+c;
        for(int i=0;i<NN;i++)s+=p[(size_t)i*NN*DD];
        g_mI[bi*DD+c]=s*(1.f/NN);
    }
}

__global__ __launch_bounds__(128) void k_PQ(const float* __restrict__ x,const float* __restrict__ ws,const float* __restrict__ bs,
    const float* __restrict__ wt,const float* __restrict__ bt,const float* __restrict__ wer,const float* __restrict__ wec){
    int bi=blockIdx.x,c=threadIdx.x;
    __shared__ float sx[DD],sj[DD],si[DD];
    sx[c]=x[bi*DD+c];sj[c]=g_mJ[bi*DD+c];si[c]=g_mI[bi*DD+c];
    __syncthreads();
    float P=bs[c],Q=bt[c];
    #pragma unroll 4
    for(int k=0;k<DD;k++){
        P+=sx[k]*ws[k*DD+c]+sj[k]*wer[k*DD+c];
        Q+=sx[k]*wt[k*DD+c]+si[k]*wec[k*DD+c];
    }
    g_P[bi*DD+c]=P;g_Q[bi*DD+c]=Q;
}

extern "C" void kernel_launch(void* const* d_in,const int* in_sizes,int n_in,void* d_out,int out_size){
    const float* node=(const float*)d_in[0];
    const float* edge=(const float*)d_in[1];
    const float* wqkvn=(const float*)d_in[3];
    const float* wqkve=(const float*)d_in[4];
    const float* lin0w=(const float*)d_in[5];
    const float* lin0b=(const float*)d_in[6];
    const float* ln0g=(const float*)d_in[7];
    const float* ln0b=(const float*)d_in[8];
    const float* ln1g=(const float*)d_in[9];
    const float* ln1b=(const float*)d_in[10];
    const float* w1=(const float*)d_in[11];
    const float* w2=(const float*)d_in[12];
    const float* b2=(const float*)d_in[13];
    const float* e0we=(const float*)d_in[14];
    const float* e0be=(const float*)d_in[15];
    const float* e0ws=(const float*)d_in[16];
    const float* e0bs=(const float*)d_in[17];
    const float* e0wt=(const float*)d_in[18];
    const float* e0bt=(const float*)d_in[19];
    const float* e0wer=(const float*)d_in[20];
    const float* e0wec=(const float*)d_in[21];
    const float* e0w1=(const float*)d_in[22];
    const float* e0b1=(const float*)d_in[23];
    const float* e1w1=(const float*)d_in[24];
    const float* e1w2=(const float*)d_in[25];
    const float* e1b2=(const float*)d_in[26];
    const float* eln0g=(const float*)d_in[27];
    const float* eln0b=(const float*)d_in[28];
    const float* eln1g=(const float*)d_in[29];
    const float* eln1b=(const float*)d_in[30];
    float* xout=(float*)d_out;
    float* eout=(float*)d_out+(size_t)ROWS_N*DD;

    const int SM_SMALL=131072+1024;          // fp32-A, no stage
    const int SM_STAGE=131072+132*128*4+1024;
    const int SM_B16=98304+1024;             // bf16-A, no stage
    const int SM_B16ST=98304+132*128*4+1024; // bf16-A + stage
    const int SM_BIG=196608+1024;
    cudaFuncSetAttribute(k_mm<0,false,false>,cudaFuncAttributeMaxDynamicSharedMemorySize,SM_SMALL);
    cudaFuncSetAttribute(k_mm<1,true ,false>,cudaFuncAttributeMaxDynamicSharedMemorySize,SM_SMALL);
    cudaFuncSetAttribute(k_mm<2,false,false>,cudaFuncAttributeMaxDynamicSharedMemorySize,SM_STAGE);
    cudaFuncSetAttribute(k_mm<0,false,true >,cudaFuncAttributeMaxDynamicSharedMemorySize,SM_B16);
    cudaFuncSetAttribute(k_mm<4,false,true >,cudaFuncAttributeMaxDynamicSharedMemorySize,SM_B16ST);
    cudaFuncSetAttribute(k_mm2<6>,cudaFuncAttributeMaxDynamicSharedMemorySize,SM_BIG);
    cudaFuncSetAttribute(k_mm2<7>,cudaFuncAttributeMaxDynamicSharedMemorySize,SM_BIG);

    float *gb,*gs1,*gp,*gq2;
    uint32_t *gqb,*ghb;
    cudaGetSymbolAddress((void**)&gb,g_buf);
    cudaGetSymbolAddress((void**)&gs1,g_s1);
    cudaGetSymbolAddress((void**)&gqb,g_qkvb);
    cudaGetSymbolAddress((void**)&ghb,g_hb);
    cudaGetSymbolAddress((void**)&gp,g_P);
    cudaGetSymbolAddress((void**)&gq2,g_Q);

    k_qkvn<<<ROWS_N,384>>>(node,wqkvn);
    // qkve -> bf16 (two fused N=256 passes)
    for(int q=0;q<2;q++)
        k_mm2<6><<<148,512,SM_BIG>>>(edge,32, wqkve,512,q*256, gqb,256,q*128);
    k_means<<<dim3(ROWS_N,2),128>>>(edge);
    k_attn<<<ROWS_N*8/4,128>>>();
    k_node<<<ROWS_N,128>>>(node,lin0w,lin0b,ln0g,ln0b,ln1g,ln1b,w1,w2,b2,xout);
    k_PQ<<<ROWS_N,128>>>(xout,e0ws,e0bs,e0wt,e0bt,e0wer,e0wec);
    // e1 pass1: edge @ We[0:128] -> g_s1 fp32
    k_mm<0,false,false><<<148,512,SM_SMALL>>>(edge,32,0, e0we,128,0, gs1,128,0, nullptr,nullptr,nullptr,nullptr);
    // e1 pass2: edgeT @ We[128:256] + g_s1 + be + P + Q -> gelu -> g_buf fp32
    k_mm<1,true ,false><<<148,512,SM_SMALL>>>(edge,32,0, e0we+(size_t)128*128,128,0, gb,128,0, gs1,e0be,gp,gq2);
    // e2: LN(edge + g_buf@W1 + b1) -> eout
    k_mm<2,false,false><<<148,512,SM_STAGE>>>(gb,32,0, e0w1,128,0, eout,128,0, edge,e0b1,eln0g,eln0b);
    // e3: h = gelu(eout @ e1w1), N=256 -> bf16 g_hb (stride 128 u32)
    k_mm2<7><<<148,512,SM_BIG>>>(eout,32, e1w1,256,0, ghb,128,0);
    // e4 pass1: h[:,0:128](bf16) @ W2[0:128] -> g_s1 fp32 scratch
    k_mm<0,false,true ><<<148,512,SM_B16>>>((const float*)ghb,32,0, e1w2,128,0, gs1,128,0, nullptr,nullptr,nullptr,nullptr);
    // e4 pass2: LN(eout + g_s1 + h[:,128:256](bf16)@W2[128:256] + b2) -> eout in-place
    k_mm<4,false,true ><<<148,512,SM_B16ST>>>((const float*)ghb,32,16, e1w2+(size_t)128*128,128,0, eout,128,0, gs1,e1b2,eln1g,eln1b);
}

// round 17
// speedup vs baseline: 1.8531x; 1.0340x over previous
#include <cuda_runtime.h>
#include <math.h>
#include <stdint.h>

#define NB 2
#define NN 384
#define DD 128
#define NSQ (NN*NN)
#define ROWS_E (NB*NSQ)
#define ROWS_N (NB*NN)
#define T128 (ROWS_E/128)    // 2304
#define SCALE 0.08838834764831845f

__device__ __align__(256) float g_qkvn[ROWS_N*384];
__device__ __align__(256) uint32_t g_qkvb[(size_t)ROWS_E*256];   // bf16 qkve
__device__ __align__(256) float g_attn[ROWS_N*DD];
__device__ __align__(256) float g_mJ[ROWS_N*DD];
__device__ __align__(256) float g_mI[ROWS_N*DD];
__device__ __align__(256) float g_P[ROWS_N*DD];
__device__ __align__(256) float g_Q[ROWS_N*DD];
__device__ __align__(256) uint32_t g_bufb[(size_t)ROWS_E*64];    // bf16 e1-out
__device__ __align__(256) uint32_t g_eb[(size_t)ROWS_E*64];      // bf16 eout copy
__device__ __align__(256) float g_s1[(size_t)ROWS_E*DD];         // fp32 scratch
__device__ __align__(256) uint32_t g_hb[(size_t)ROWS_E*128];     // bf16 h

__device__ __forceinline__ float geluf(float x){return 0.5f*x*(1.f+erff(x*0.70710678118654752f));}
__device__ __forceinline__ float wsum(float v){
    #pragma unroll
    for(int o=16;o;o>>=1)v+=__shfl_xor_sync(0xffffffffu,v,o);return v;}
__device__ __forceinline__ float wmax(float v){
    #pragma unroll
    for(int o=16;o;o>>=1)v=fmaxf(v,__shfl_xor_sync(0xffffffffu,v,o));return v;}
__device__ __forceinline__ float uaf(uint32_t u){return __uint_as_float(u);}
__device__ __forceinline__ float2 upbf(uint32_t u){return make_float2(uaf(u<<16),uaf(u&0xffff0000u));}
__device__ __forceinline__ uint32_t pkbf(float a,float b){uint32_t r;asm("cvt.rn.bf16x2.f32 %0,%1,%2;":"=r"(r):"f"(b),"f"(a));return r;}

__device__ __forceinline__ uint32_t smem_u32(const void* p){
    uint32_t a;asm("{ .reg .u64 t; cvta.to.shared.u64 t, %1; cvt.u32.u64 %0, t; }":"=r"(a):"l"(p));return a;}
__device__ __forceinline__ void split2(float a,float b,uint32_t&h,uint32_t&l){
    asm("cvt.rn.bf16x2.f32 %0,%1,%2;":"=r"(h):"f"(b),"f"(a));
    float ha=__uint_as_float(h<<16),hb=__uint_as_float(h&0xffff0000u);
    float la=a-ha,lb=b-hb;
    asm("cvt.rn.bf16x2.f32 %0,%1,%2;":"=r"(l):"f"(lb),"f"(la));}
__device__ __forceinline__ void ldsm4(uint32_t&r0,uint32_t&r1,uint32_t&r2,uint32_t&r3,uint32_t a){
    asm volatile("ldmatrix.sync.aligned.m8n8.x4.shared.b16 {%0,%1,%2,%3},[%4];"
        :"=r"(r0),"=r"(r1),"=r"(r2),"=r"(r3):"r"(a));}
__device__ __forceinline__ void mma16816(float* d,const uint32_t* a,uint32_t b0,uint32_t b1){
    asm volatile("mma.sync.aligned.m16n8k16.row.col.f32.bf16.bf16.f32 "
        "{%0,%1,%2,%3},{%4,%5,%6,%7},{%8,%9},{%0,%1,%2,%3};"
        :"+f"(d[0]),"+f"(d[1]),"+f"(d[2]),"+f"(d[3])
        :"r"(a[0]),"r"(a[1]),"r"(a[2]),"r"(a[3]),"r"(b0),"r"(b1));}

// fp32 tile -> hi/lo bf16 smem (512 thr, 4/row)
template<bool TRANS>
__device__ __forceinline__ void convA(const float* __restrict__ A,int a_s4,int a_c4,
                                      size_t t,char* hi,char* lo,int tid){
    size_t r0=t*128;
    int m=tid>>2,qt=tid&3;
    const float4* src;
    if(TRANS){
        int bb=(int)(r0/NSQ),rem=(int)(r0%NSQ),iI=rem/NN,j0=rem%NN;
        src=(const float4*)A+((size_t)(bb*NN+(j0+m))*NN+iI)*32+qt*8;
    }else{
        src=(const float4*)A+(r0+m)*(size_t)a_s4+a_c4+qt*8;
    }
    char* rh=hi+m*256;char* rl=lo+m*256;
    int x7=m&7;
    #pragma unroll
    for(int i=0;i<8;i++){
        float4 x=__ldg(src+i);
        uint32_t h0,l0,h1,l1;
        split2(x.x,x.y,h0,l0);split2(x.z,x.w,h1,l1);
        int ig=qt*8+i;
        int kp0=ig*2,kp1=ig*2+1;
        uint32_t s0=(uint32_t)((((kp0>>2)^x7)<<4)+((kp0&3)<<2));
        uint32_t s1=(uint32_t)((((kp1>>2)^x7)<<4)+((kp1&3)<<2));
        *(uint32_t*)(rh+s0)=h0;*(uint32_t*)(rh+s1)=h1;
        *(uint32_t*)(rl+s0)=l0;*(uint32_t*)(rl+s1)=l1;
    }
}
// bf16 tile copy loader (rows of a_s4 uint4; chunk offset a_c4 uint4)
__device__ __forceinline__ void convB16(const uint32_t* __restrict__ A,int a_s4,int a_c4,
                                        size_t t,char* hi,int tid){
    size_t r0=t*128;
    int m=tid>>2,q=tid&3,x7=m&7;
    const uint4* src=(const uint4*)A+(r0+m)*(size_t)a_s4+a_c4+q*4;
    char* rh=hi+m*256;
    #pragma unroll
    for(int i=0;i<4;i++){
        int g=q*4+i;
        *(uint4*)(rh+((g^x7)<<4))=__ldg(src+i);
    }
}

// ===================== unfused GEMM (N=128, 512 thr, warp 32x32) =====================
// MODE: 0=RAW fp32, 1=E1 gelu(c+b+add1+P+Q) -> bf16 pack, 2=LN(c+b+add1) staged (+bf16 copy to sdst), 4=LN(c+b+add1+out) staged
template<int MODE,bool TRANS,bool AB16>
__global__ __launch_bounds__(512,1) void k_mm(
    const float* __restrict__ A,int a_s4,int a_c4,
    const float* __restrict__ W,int w_ld,int w_cf,
    float* __restrict__ out,int o_st,int o_cf,
    const float* __restrict__ add1,const float* __restrict__ bias,
    const float* __restrict__ lng,const float* __restrict__ lnb,
    uint32_t* __restrict__ sdst)
{
    extern __shared__ char dyn[];
    char* base=(char*)((((uintptr_t)dyn)+1023)&~(uintptr_t)1023);
    char* Ah=base;
    char* Al=AB16?nullptr:base+32768;
    char* Wh=AB16?base+32768:base+65536;
    char* Wl=Wh+32768;
    float* stage=(float*)(Wl+32768);
    int tid=threadIdx.x,wp=tid>>5,lane=tid&31;
    int wr=wp>>2,wc=wp&3;
    int l15=lane&15,kh=lane>>4,x7=l15&7;

    {
        int n=tid&127,kq=(tid>>7)*32;
        char* rh=Wh+n*256;char* rl=Wl+n*256;
        int nx7=n&7;
        #pragma unroll
        for(int kk=0;kk<32;kk+=2){
            int k=kq+kk;
            float w0=__ldg(W+(size_t)k*w_ld+w_cf+n);
            float w1=__ldg(W+(size_t)(k+1)*w_ld+w_cf+n);
            uint32_t h2,l2;split2(w0,w1,h2,l2);
            int kp=k>>1;
            uint32_t s=(uint32_t)((((kp>>2)^nx7)<<4)+((kp&3)<<2));
            *(uint32_t*)(rh+s)=h2;*(uint32_t*)(rl+s)=l2;
        }
    }
    size_t t=blockIdx.x;
    if(t<T128){
        if(AB16)convB16((const uint32_t*)A,a_s4,a_c4,t,Ah,tid);
        else convA<TRANS>(A,a_s4,a_c4,t,Ah,Al,tid);
    }
    __syncthreads();
    uint32_t AhU=smem_u32(Ah),AlU=AB16?0:smem_u32(Al),WhU=smem_u32(Wh),WlU=smem_u32(Wl);
    uint32_t rowA0=(uint32_t)(wr*32+l15)*256,rowA1=(uint32_t)(wr*32+16+l15)*256;
    uint32_t rowB0=(uint32_t)(wc*32+l15)*256,rowB1=(uint32_t)(wc*32+16+l15)*256;

    for(;t<T128;t+=gridDim.x){
        float acc[2][4][4];
        #pragma unroll
        for(int mi=0;mi<2;mi++)
            #pragma unroll
            for(int ni=0;ni<4;ni++){acc[mi][ni][0]=0.f;acc[mi][ni][1]=0.f;acc[mi][ni][2]=0.f;acc[mi][ni][3]=0.f;}
        #pragma unroll 2
        for(int ks=0;ks<8;ks++){
            uint32_t coff=(uint32_t)(((ks*2+kh)^x7)<<4);
            uint32_t ah[2][4],al[2][4];
            ldsm4(ah[0][0],ah[0][1],ah[0][2],ah[0][3],AhU+rowA0+coff);
            ldsm4(ah[1][0],ah[1][1],ah[1][2],ah[1][3],AhU+rowA1+coff);
            if(!AB16){
                ldsm4(al[0][0],al[0][1],al[0][2],al[0][3],AlU+rowA0+coff);
                ldsm4(al[1][0],al[1][1],al[1][2],al[1][3],AlU+rowA1+coff);
            }
            uint32_t bh0,bh1,bh2,bh3,bl0,bl1,bl2,bl3;
            ldsm4(bh0,bh1,bh2,bh3,WhU+rowB0+coff);
            ldsm4(bl0,bl1,bl2,bl3,WlU+rowB0+coff);
            #pragma unroll
            for(int mi=0;mi<2;mi++){
                mma16816(acc[mi][0],ah[mi],bh0,bh2);
                if(!AB16)mma16816(acc[mi][0],al[mi],bh0,bh2);
                mma16816(acc[mi][0],ah[mi],bl0,bl2);
                mma16816(acc[mi][1],ah[mi],bh1,bh3);
                if(!AB16)mma16816(acc[mi][1],al[mi],bh1,bh3);
                mma16816(acc[mi][1],ah[mi],bl1,bl3);
            }
            ldsm4(bh0,bh1,bh2,bh3,WhU+rowB1+coff);
            ldsm4(bl0,bl1,bl2,bl3,WlU+rowB1+coff);
            #pragma unroll
            for(int mi=0;mi<2;mi++){
                mma16816(acc[mi][2],ah[mi],bh0,bh2);
                if(!AB16)mma16816(acc[mi][2],al[mi],bh0,bh2);
                mma16816(acc[mi][2],ah[mi],bl0,bl2);
                mma16816(acc[mi][3],ah[mi],bh1,bh3);
                if(!AB16)mma16816(acc[mi][3],al[mi],bh1,bh3);
                mma16816(acc[mi][3],ah[mi],bl1,bl3);
            }
        }
        size_t r0=t*128;
        if constexpr(MODE==2||MODE==4){
            #pragma unroll
            for(int mi=0;mi<2;mi++){
                int row=wr*32+mi*16+(lane>>2);
                #pragma unroll
                for(int ni=0;ni<4;ni++){
                    int col=wc*32+ni*8+(lane&3)*2;
                    *(float2*)&stage[row*132+col]=make_float2(acc[mi][ni][0],acc[mi][ni][1]);
                    *(float2*)&stage[(row+8)*132+col]=make_float2(acc[mi][ni][2],acc[mi][ni][3]);
                }
            }
        }
        __syncthreads();
        size_t tn=t+gridDim.x;
        if(tn<T128){
            if(AB16)convB16((const uint32_t*)A,a_s4,a_c4,tn,Ah,tid);
            else convA<TRANS>(A,a_s4,a_c4,tn,Ah,Al,tid);
        }
        if constexpr(MODE==0){
            #pragma unroll
            for(int ni=0;ni<4;ni++){
                int col=o_cf+wc*32+ni*8+(lane&3)*2;
                #pragma unroll
                for(int mi=0;mi<2;mi++){
                    int rl=wr*32+mi*16+(lane>>2);
                    *(float2*)(out+((size_t)r0+rl)*o_st+col)=*(float2*)&acc[mi][ni][0];
                    *(float2*)(out+((size_t)r0+rl+8)*o_st+col)=*(float2*)&acc[mi][ni][2];
                }
            }
        }else if constexpr(MODE==1){
            uint32_t* outu=(uint32_t*)out;
            int bb=(int)(r0/NSQ),rem=(int)(r0%NSQ),iI=rem/NN,j0=rem%NN;
            const float* Pr=lng+(size_t)(bb*NN+iI)*128;
            #pragma unroll
            for(int ni=0;ni<4;ni++){
                int col=wc*32+ni*8+(lane&3)*2;
                int kp=col>>1;
                float2 p2=*(const float2*)(Pr+col);
                float2 b2=*(const float2*)(bias+col);
                #pragma unroll
                for(int mi=0;mi<2;mi++){
                    int rl=wr*32+mi*16+(lane>>2);
                    #pragma unroll
                    for(int h=0;h<2;h++){
                        int row=rl+h*8;
                        float2 c=*(float2*)&acc[mi][ni][h*2];
                        float2 q2=*(const float2*)(lnb+((size_t)(bb*NN+j0+row))*128+col);
                        float2 a2=*(const float2*)(add1+((size_t)r0+row)*128+col);
                        float ox=geluf(c.x+b2.x+p2.x+q2.x+a2.x);
                        float oy=geluf(c.y+b2.y+p2.y+q2.y+a2.y);
                        outu[((size_t)r0+row)*o_st+kp]=pkbf(ox,oy);
                    }
                }
            }
        }else{
            int m=tid>>2,qt=tid&3;
            size_t row=r0+m;
            const float* srow=stage+m*132+qt*32;
            float* orow=out+row*(size_t)o_st+o_cf+qt*32;
            const float* a1=add1+row*128+qt*32;
            const float* bi=bias+qt*32;
            float v[32];
            float s=0.f;
            #pragma unroll
            for(int n=0;n<32;n+=4){
                float4 c=*(const float4*)(srow+n);
                float4 a4=*(const float4*)(a1+n),b4=*(const float4*)(bi+n);
                v[n]=c.x+b4.x+a4.x;v[n+1]=c.y+b4.y+a4.y;
                v[n+2]=c.z+b4.z+a4.z;v[n+3]=c.w+b4.w+a4.w;
                if constexpr(MODE==4){
                    float4 t4=*(const float4*)(orow+n);
                    v[n]+=t4.x;v[n+1]+=t4.y;v[n+2]+=t4.z;v[n+3]+=t4.w;
                }
                s+=v[n]+v[n+1]+v[n+2]+v[n+3];
            }
            s+=__shfl_xor_sync(0xffffffffu,s,1);
            s+=__shfl_xor_sync(0xffffffffu,s,2);
            float mean=s*(1.f/128.f),s2=0.f;
            #pragma unroll
            for(int n=0;n<32;n++){v[n]-=mean;s2+=v[n]*v[n];}
            s2+=__shfl_xor_sync(0xffffffffu,s2,1);
            s2+=__shfl_xor_sync(0xffffffffu,s2,2);
            float rs=rsqrtf(s2*(1.f/128.f)+1e-5f);
            const float* gg=lng+qt*32;const float* bb2=lnb+qt*32;
            #pragma unroll
            for(int n=0;n<32;n+=4){
                float4 g4=*(const float4*)(gg+n),b4=*(const float4*)(bb2+n);
                float4 o;
                o.x=v[n]*rs*g4.x+b4.x;o.y=v[n+1]*rs*g4.y+b4.y;
                o.z=v[n+2]*rs*g4.z+b4.z;o.w=v[n+3]*rs*g4.w+b4.w;
                *(float4*)(orow+n)=o;
                if constexpr(MODE==2){
                    if(sdst){
                        int kp=qt*16+(n>>1);
                        uint32_t* dh=sdst+row*64+kp;
                        dh[0]=pkbf(o.x,o.y);dh[1]=pkbf(o.z,o.w);
                    }
                }
            }
        }
        __syncthreads();
    }
}

// ===================== fused GEMM (N=256, 512 thr) -> bf16 out =====================
// MODE: 6=RAW bf16 pack, 7=GELU bf16 pack
template<int MODE,bool AB16>
__global__ __launch_bounds__(512,1) void k_mm2(
    const float* __restrict__ A,int a_s4,
    const float* __restrict__ W,int w_ld,int w_cf,
    uint32_t* __restrict__ outu,int o_stu,int o_cfu)
{
    extern __shared__ char dyn[];
    char* base=(char*)((((uintptr_t)dyn)+1023)&~(uintptr_t)1023);
    char* Ah=base;
    char* Al=AB16?nullptr:base+32768;
    char* Wb0=AB16?base+32768:base+65536;
    int tid=threadIdx.x,wp=tid>>5,lane=tid&31;
    int wr=wp>>2,wc=wp&3;
    int l15=lane&15,kh=lane>>4,x7=l15&7;

    {
        int n2=tid&255,nb=n2>>7,n=n2&127,kq=(tid>>8)*64;
        char* rh=Wb0+nb*65536+n*256;char* rl=rh+32768;
        int nx7=n&7;
        #pragma unroll
        for(int kk=0;kk<64;kk+=2){
            int k=kq+kk;
            float w0=__ldg(W+(size_t)k*w_ld+w_cf+nb*128+n);
            float w1=__ldg(W+(size_t)(k+1)*w_ld+w_cf+nb*128+n);
            uint32_t h2,l2;split2(w0,w1,h2,l2);
            int kp=k>>1;
            uint32_t s=(uint32_t)((((kp>>2)^nx7)<<4)+((kp&3)<<2));
            *(uint32_t*)(rh+s)=h2;*(uint32_t*)(rl+s)=l2;
        }
    }
    size_t t=blockIdx.x;
    if(t<T128){
        if(AB16)convB16((const uint32_t*)A,a_s4,0,t,Ah,tid);
        else convA<false>(A,a_s4,0,t,Ah,Al,tid);
    }
    __syncthreads();
    uint32_t AhU=smem_u32(Ah),AlU=AB16?0:smem_u32(Al);
    uint32_t WhU[2]={smem_u32(Wb0),smem_u32(Wb0+65536)};
    uint32_t WlU[2]={WhU[0]+32768,WhU[1]+32768};
    uint32_t rowA0=(uint32_t)(wr*32+l15)*256,rowA1=(uint32_t)(wr*32+16+l15)*256;
    uint32_t rowB0=(uint32_t)(wc*32+l15)*256,rowB1=(uint32_t)(wc*32+16+l15)*256;

    for(;t<T128;t+=gridDim.x){
        float acc[2][2][4][4];
        #pragma unroll
        for(int nb=0;nb<2;nb++)
            #pragma unroll
            for(int mi=0;mi<2;mi++)
                #pragma unroll
                for(int ni=0;ni<4;ni++){acc[nb][mi][ni][0]=0.f;acc[nb][mi][ni][1]=0.f;acc[nb][mi][ni][2]=0.f;acc[nb][mi][ni][3]=0.f;}
        for(int ks=0;ks<8;ks++){
            uint32_t coff=(uint32_t)(((ks*2+kh)^x7)<<4);
            uint32_t ah[2][4],al[2][4];
            ldsm4(ah[0][0],ah[0][1],ah[0][2],ah[0][3],AhU+rowA0+coff);
            ldsm4(ah[1][0],ah[1][1],ah[1][2],ah[1][3],AhU+rowA1+coff);
            if(!AB16){
                ldsm4(al[0][0],al[0][1],al[0][2],al[0][3],AlU+rowA0+coff);
                ldsm4(al[1][0],al[1][1],al[1][2],al[1][3],AlU+rowA1+coff);
            }
            #pragma unroll
            for(int nb=0;nb<2;nb++){
                uint32_t bh0,bh1,bh2,bh3,bl0,bl1,bl2,bl3;
                ldsm4(bh0,bh1,bh2,bh3,WhU[nb]+rowB0+coff);
                ldsm4(bl0,bl1,bl2,bl3,WlU[nb]+rowB0+coff);
                #pragma unroll
                for(int mi=0;mi<2;mi++){
                    mma16816(acc[nb][mi][0],ah[mi],bh0,bh2);
                    if(!AB16)mma16816(acc[nb][mi][0],al[mi],bh0,bh2);
                    mma16816(acc[nb][mi][0],ah[mi],bl0,bl2);
                    mma16816(acc[nb][mi][1],ah[mi],bh1,bh3);
                    if(!AB16)mma16816(acc[nb][mi][1],al[mi],bh1,bh3);
                    mma16816(acc[nb][mi][1],ah[mi],bl1,bl3);
                }
                ldsm4(bh0,bh1,bh2,bh3,WhU[nb]+rowB1+coff);
                ldsm4(bl0,bl1,bl2,bl3,WlU[nb]+rowB1+coff);
                #pragma unroll
                for(int mi=0;mi<2;mi++){
                    mma16816(acc[nb][mi][2],ah[mi],bh0,bh2);
                    if(!AB16)mma16816(acc[nb][mi][2],al[mi],bh0,bh2);
                    mma16816(acc[nb][mi][2],ah[mi],bl0,bl2);
                    mma16816(acc[nb][mi][3],ah[mi],bh1,bh3);
                    if(!AB16)mma16816(acc[nb][mi][3],al[mi],bh1,bh3);
                    mma16816(acc[nb][mi][3],ah[mi],bl1,bl3);
                }
            }
        }
        __syncthreads();
        size_t tn=t+gridDim.x;
        if(tn<T128){
            if(AB16)convB16((const uint32_t*)A,a_s4,0,tn,Ah,tid);
            else convA<false>(A,a_s4,0,tn,Ah,Al,tid);
        }
        size_t r0=t*128;
        #pragma unroll
        for(int nb=0;nb<2;nb++){
            #pragma unroll
            for(int ni=0;ni<4;ni++){
                int kp=o_cfu+(nb*128+wc*32+ni*8+(lane&3)*2)/2;
                #pragma unroll
                for(int mi=0;mi<2;mi++){
                    int rl=wr*32+mi*16+(lane>>2);
                    float a0=acc[nb][mi][ni][0],a1=acc[nb][mi][ni][1];
                    float a2=acc[nb][mi][ni][2],a3=acc[nb][mi][ni][3];
                    if constexpr(MODE==7){a0=geluf(a0);a1=geluf(a1);a2=geluf(a2);a3=geluf(a3);}
                    outu[((size_t)r0+rl)*o_stu+kp]=pkbf(a0,a1);
                    outu[((size_t)r0+rl+8)*o_stu+kp]=pkbf(a2,a3);
                }
            }
        }
        __syncthreads();
    }
}

// ===================== small kernels =====================
__global__ __launch_bounds__(384) void k_qkvn(const float* __restrict__ node,const float* __restrict__ W){
    int row=blockIdx.x,c=threadIdx.x;
    __shared__ float s[DD];
    if(c<DD)s[c]=node[row*DD+c];
    __syncthreads();
    float a=0.f;
    #pragma unroll 8
    for(int k=0;k<DD;k++)a+=s[k]*W[k*384+c];
    g_qkvn[row*384+c]=a;
}

__global__ __launch_bounds__(128) void k_attn(){
    int w=threadIdx.x>>5,lane=threadIdx.x&31;
    int gw=blockIdx.x*4+w;
    int b=gw/(8*NN),rr=gw%(8*NN),h=rr/NN,i=rr%NN;
    const float* qb=g_qkvn+(b*NN+i)*384+h*48;
    float qv[16];
    #pragma unroll
    for(int c=0;c<16;c++)qv[c]=qb[c];
    const uint32_t* eb=g_qkvb+((size_t)(b*NN+i)*NN)*256+h*32;
    float dl[12];
    #pragma unroll
    for(int t=0;t<12;t++){
        int j=lane+32*t;
        const uint4* e4=(const uint4*)(eb+(size_t)j*256);
        uint32_t EQ[8],EK[8];
        *(uint4*)EQ=e4[0];*(uint4*)(EQ+4)=e4[1];
        *(uint4*)EK=e4[2];*(uint4*)(EK+4)=e4[3];
        const float* kn=g_qkvn+(b*NN+j)*384+h*48+16;
        float d=0.f;
        #pragma unroll
        for(int u=0;u<8;u++){
            float2 eq=upbf(EQ[u]),ek=upbf(EK[u]);
            d+=(qv[2*u]+eq.x)*(kn[2*u]+ek.x)+(qv[2*u+1]+eq.y)*(kn[2*u+1]+ek.y);
        }
        dl[t]=d*SCALE;
    }
    float m=dl[0];
    #pragma unroll
    for(int t=1;t<12;t++)m=fmaxf(m,dl[t]);
    m=wmax(m);
    float s=0.f,out[16];
    #pragma unroll
    for(int c=0;c<16;c++)out[c]=0.f;
    #pragma unroll
    for(int t=0;t<12;t++){
        int j=lane+32*t;
        float p=__expf(dl[t]-m);s+=p;
        const uint4* e4=(const uint4*)(eb+(size_t)j*256);
        uint32_t EV[8],EM[8];
        *(uint4*)EV=e4[4];*(uint4*)(EV+4)=e4[5];
        *(uint4*)EM=e4[6];*(uint4*)(EM+4)=e4[7];
        const float* vn=g_qkvn+(b*NN+j)*384+h*48+32;
        #pragma unroll
        for(int u=0;u<8;u++){
            float2 ev=upbf(EV[u]),em=upbf(EM[u]);
            out[2*u]+=p*(vn[2*u]*em.x+ev.x);
            out[2*u+1]+=p*(vn[2*u+1]*em.y+ev.y);
        }
    }
    s=wsum(s);
    float inv=1.f/s;
    #pragma unroll
    for(int c=0;c<16;c++){
        float v=wsum(out[c]);
        if(lane==0)g_attn[(b*NN+i)*DD+h*16+c]=v*inv;
    }
}

__global__ __launch_bounds__(128) void k_node(const float* __restrict__ node,const float* __restrict__ w0,const float* __restrict__ b0,
    const float* __restrict__ g0,const float* __restrict__ be0,const float* __restrict__ g1,const float* __restrict__ be1,
    const float* __restrict__ w1,const float* __restrict__ w2,const float* __restrict__ b2,float* __restrict__ x){
    int row=blockIdx.x,c=threadIdx.x;
    __shared__ float sa[DD],sx[DD],sh[256],sr[8];
    sa[c]=g_attn[row*DD+c];
    __syncthreads();
    float y=b0[c];
    #pragma unroll 4
    for(int k=0;k<DD;k++)y+=sa[k]*w0[k*DD+c];
    float r=node[row*DD+c]+y;
    float t=wsum(r);if((c&31)==0)sr[c>>5]=t;__syncthreads();
    float mean=(sr[0]+sr[1]+sr[2]+sr[3])*(1.f/DD);
    float d=r-mean;
    t=wsum(d*d);if((c&31)==0)sr[4+(c>>5)]=t;__syncthreads();
    float x0=d*rsqrtf((sr[4]+sr[5]+sr[6]+sr[7])*(1.f/DD)+1e-5f)*g0[c]+be0[c];
    sx[c]=x0;__syncthreads();
    float h0=0.f,h1=0.f;
    #pragma unroll 4
    for(int k=0;k<DD;k++){float v=sx[k];h0+=v*w1[k*256+c];h1+=v*w1[k*256+c+128];}
    sh[c]=geluf(h0);sh[c+128]=geluf(h1);
    __syncthreads();
    float z=b2[c];
    #pragma unroll 4
    for(int k=0;k<256;k++)z+=sh[k]*w2[k*DD+c];
    float r2=x0+z;
    __syncthreads();
    t=wsum(r2);if((c&31)==0)sr[c>>5]=t;__syncthreads();
    float m2=(sr[0]+sr[1]+sr[2]+sr[3])*(1.f/DD);
    float d2=r2-m2;
    t=wsum(d2*d2);if((c&31)==0)sr[4+(c>>5)]=t;__syncthreads();
    x[row*DD+c]=d2*rsqrtf((sr[4]+sr[5]+sr[6]+sr[7])*(1.f/DD)+1e-5f)*g1[c]+be1[c];
}

__global__ __launch_bounds__(128) void k_means(const float* __restrict__ edge){
    int bi=blockIdx.x,c=threadIdx.x,b=bi/NN,r=bi%NN;
    float s=0.f;
    if(blockIdx.y==0){
        const float* p=edge+((size_t)(b*NN+r)*NN)*DD+c;
        for(int j=0;j<NN;j++)s+=p[(size_t)j*DD];
        g_mJ[bi*DD+c]=s*(1.f/NN);
    }else{
        const float* p=edge+((size_t)b*NSQ+r)*DD+c;
        for(int i=0;i<NN;i++)s+=p[(size_t)i*NN*DD];
        g_mI[bi*DD+c]=s*(1.f/NN);
    }
}

__global__ __launch_bounds__(128) void k_PQ(const float* __restrict__ x,const float* __restrict__ ws,const float* __restrict__ bs,
    const float* __restrict__ wt,const float* __restrict__ bt,const float* __restrict__ wer,const float* __restrict__ wec){
    int bi=blockIdx.x,c=threadIdx.x;
    __shared__ float sx[DD],sj[DD],si[DD];
    sx[c]=x[bi*DD+c];sj[c]=g_mJ[bi*DD+c];si[c]=g_mI[bi*DD+c];
    __syncthreads();
    float P=bs[c],Q=bt[c];
    #pragma unroll 4
    for(int k=0;k<DD;k++){
        P+=sx[k]*ws[k*DD+c]+sj[k]*wer[k*DD+c];
        Q+=sx[k]*wt[k*DD+c]+si[k]*wec[k*DD+c];
    }
    g_P[bi*DD+c]=P;g_Q[bi*DD+c]=Q;
}

extern "C" void kernel_launch(void* const* d_in,const int* in_sizes,int n_in,void* d_out,int out_size){
    const float* node=(const float*)d_in[0];
    const float* edge=(const float*)d_in[1];
    const float* wqkvn=(const float*)d_in[3];
    const float* wqkve=(const float*)d_in[4];
    const float* lin0w=(const float*)d_in[5];
    const float* lin0b=(const float*)d_in[6];
    const float* ln0g=(const float*)d_in[7];
    const float* ln0b=(const float*)d_in[8];
    const float* ln1g=(const float*)d_in[9];
    const float* ln1b=(const float*)d_in[10];
    const float* w1=(const float*)d_in[11];
    const float* w2=(const float*)d_in[12];
    const float* b2=(const float*)d_in[13];
    const float* e0we=(const float*)d_in[14];
    const float* e0be=(const float*)d_in[15];
    const float* e0ws=(const float*)d_in[16];
    const float* e0bs=(const float*)d_in[17];
    const float* e0wt=(const float*)d_in[18];
    const float* e0bt=(const float*)d_in[19];
    const float* e0wer=(const float*)d_in[20];
    const float* e0wec=(const float*)d_in[21];
    const float* e0w1=(const float*)d_in[22];
    const float* e0b1=(const float*)d_in[23];
    const float* e1w1=(const float*)d_in[24];
    const float* e1w2=(const float*)d_in[25];
    const float* e1b2=(const float*)d_in[26];
    const float* eln0g=(const float*)d_in[27];
    const float* eln0b=(const float*)d_in[28];
    const float* eln1g=(const float*)d_in[29];
    const float* eln1b=(const float*)d_in[30];
    float* xout=(float*)d_out;
    float* eout=(float*)d_out+(size_t)ROWS_N*DD;

    const int SM_SMALL=131072+1024;              // fp32-A, no stage
    const int SM_B16=98304+1024;                 // bf16-A, no stage
    const int SM_B16ST=98304+132*128*4+1024;     // bf16-A + stage
    const int SM_BIG=196608+1024;                // fp32-A fused
    const int SM_BIGB16=163840+1024;             // bf16-A fused
    cudaFuncSetAttribute(k_mm<0,false,false>,cudaFuncAttributeMaxDynamicSharedMemorySize,SM_SMALL);
    cudaFuncSetAttribute(k_mm<1,true ,false>,cudaFuncAttributeMaxDynamicSharedMemorySize,SM_SMALL);
    cudaFuncSetAttribute(k_mm<2,false,true >,cudaFuncAttributeMaxDynamicSharedMemorySize,SM_B16ST);
    cudaFuncSetAttribute(k_mm<0,false,true >,cudaFuncAttributeMaxDynamicSharedMemorySize,SM_B16);
    cudaFuncSetAttribute(k_mm<4,false,true >,cudaFuncAttributeMaxDynamicSharedMemorySize,SM_B16ST);
    cudaFuncSetAttribute(k_mm2<6,false>,cudaFuncAttributeMaxDynamicSharedMemorySize,SM_BIG);
    cudaFuncSetAttribute(k_mm2<7,true >,cudaFuncAttributeMaxDynamicSharedMemorySize,SM_BIGB16);

    float *gs1,*gp,*gq2;
    uint32_t *gqb,*ghb,*gbb,*geb;
    cudaGetSymbolAddress((void**)&gs1,g_s1);
    cudaGetSymbolAddress((void**)&gqb,g_qkvb);
    cudaGetSymbolAddress((void**)&ghb,g_hb);
    cudaGetSymbolAddress((void**)&gbb,g_bufb);
    cudaGetSymbolAddress((void**)&geb,g_eb);
    cudaGetSymbolAddress((void**)&gp,g_P);
    cudaGetSymbolAddress((void**)&gq2,g_Q);

    k_qkvn<<<ROWS_N,384>>>(node,wqkvn);
    // qkve -> bf16 (two fused N=256 passes, fp32-A)
    for(int q=0;q<2;q++)
        k_mm2<6,false><<<148,512,SM_BIG>>>(edge,32, wqkve,512,q*256, gqb,256,q*128);
    k_means<<<dim3(ROWS_N,2),128>>>(edge);
    k_attn<<<ROWS_N*8/4,128>>>();
    k_node<<<ROWS_N,128>>>(node,lin0w,lin0b,ln0g,ln0b,ln1g,ln1b,w1,w2,b2,xout);
    k_PQ<<<ROWS_N,128>>>(xout,e0ws,e0bs,e0wt,e0bt,e0wer,e0wec);
    // e1 pass1: edge @ We[0:128] -> g_s1 fp32
    k_mm<0,false,false><<<148,512,SM_SMALL>>>(edge,32,0, e0we,128,0, gs1,128,0, nullptr,nullptr,nullptr,nullptr,nullptr);
    // e1 pass2: edgeT @ We[128:256] + g_s1 + be + P + Q -> gelu -> bf16 g_bufb (o_st=64 u32)
    k_mm<1,true ,false><<<148,512,SM_SMALL>>>(edge,32,0, e0we+(size_t)128*128,128,0, (float*)gbb,64,0, gs1,e0be,gp,gq2, nullptr);
    // e2: LN(edge + e1(bf16)@W1 + b1) -> eout fp32 + bf16 copy -> g_eb
    k_mm<2,false,true ><<<148,512,SM_B16ST>>>((const float*)gbb,16,0, e0w1,128,0, eout,128,0, edge,e0b1,eln0g,eln0b, geb);
    // e3: h = gelu(eout(bf16) @ e1w1), N=256 -> bf16 g_hb
    k_mm2<7,true ><<<148,512,SM_BIGB16>>>((const float*)geb,16, e1w1,256,0, ghb,128,0);
    // e4 pass1: h[:,0:128](bf16) @ W2[0:128] -> g_s1 fp32 scratch
    k_mm<0,false,true ><<<148,512,SM_B16>>>((const float*)ghb,32,0, e1w2,128,0, gs1,128,0, nullptr,nullptr,nullptr,nullptr,nullptr);
    // e4 pass2: LN(eout + g_s1 + h[:,128:256](bf16)@W2[128:256] + b2) -> eout in-place
    k_mm<4,false,true ><<<148,512,SM_B16ST>>>((const float*)ghb,32,16, e1w2+(size_t)128*128,128,0, eout,128,0, gs1,e1b2,eln1g,eln1b, nullptr);
}